// round 6
// baseline (speedup 1.0000x reference)
#include <cuda_runtime.h>

#define NB   4
#define SEQ  2048
#define HID  1024
#define HD   64
#define NH   16
#define KS   4      // split-K factor for attn@V
#define INV32 0.03125f

typedef unsigned long long ull;

// packed f32x2 helpers (Blackwell double-rate fp32)
#define FMA2(acc, a, b) asm("fma.rn.f32x2 %0, %1, %2, %0;" : "+l"(acc) : "l"(a), "l"(b))
#define PACK2(d, s)     asm("mov.b64 %0, {%1, %1};" : "=l"(d) : "f"(s))
#define UNPK2(lo, hi, v) asm("mov.b64 {%0, %1}, %2;" : "=f"(lo), "=f"(hi) : "l"(v))

// ---------------- scratch ---------------------------------------------------
static __device__ float g_q[NB * SEQ * HD];
static __device__ float g_k[NB * SEQ * HD];
static __device__ float g_v[NB * SEQ * HD];
static __device__ float g_sc[(size_t)NB * SEQ * SEQ];       // raw scores
static __device__ float g_mean[NB * SEQ];
static __device__ float g_isig[NB * SEQ];
static __device__ float g_esp[KS][NB * SEQ];                // partial expsums
static __device__ float g_hp[KS][NB * SEQ * HD];            // split-K head partials
static __device__ float g_head[NB * SEQ * HD];
static __device__ float g_wf[HD * HID];                     // folded Wout

// ---------------- Wfold: wf[d][j] = sum_h Wout[h*64+d][j] --------------------
__global__ __launch_bounds__(256) void k_wfold(const float* __restrict__ Wout) {
    int idx = blockIdx.x * 256 + threadIdx.x;
    if (idx >= HD * HID) return;
    int d = idx >> 10, j = idx & 1023;
    float s = 0.f;
#pragma unroll
    for (int h = 0; h < NH; h++) s += Wout[(h * HD + d) * HID + j];
    g_wf[idx] = s;
}

// ---------------- projections: O = X @ W + b  (M=8192, N=64, K=1024) --------
// BM=128, BN=64, BK=32, 256 threads, 8x4 per thread (packed pairs along M).
__global__ __launch_bounds__(256) void k_proj(
    const float* __restrict__ Xq, const float* __restrict__ Xk, const float* __restrict__ Xv,
    const float* __restrict__ Wq, const float* __restrict__ Wk, const float* __restrict__ Wv,
    const float* __restrict__ Bq, const float* __restrict__ Bk, const float* __restrict__ Bv)
{
    __shared__ __align__(16) float As[32][132];  // [k][m]
    __shared__ __align__(16) float Bs[32][68];   // [k][n]

    const int which = blockIdx.y;
    const float* X  = (which == 0) ? Xq : (which == 1) ? Xk : Xv;
    const float* W  = (which == 0) ? Wq : (which == 1) ? Wk : Wv;
    const float* Bb = (which == 0) ? Bq : (which == 1) ? Bk : Bv;
    float*       O  = (which == 0) ? g_q : (which == 1) ? g_k : g_v;

    const int m0 = blockIdx.x * 128;
    const int tid = threadIdx.x, tx = tid & 15, ty = tid >> 4;
    ull acc[4][4] = {};   // [m-pair][n]

    for (int k0 = 0; k0 < HID; k0 += 32) {
        __syncthreads();
#pragma unroll
        for (int t = tid; t < 1024; t += 256) {        // X tile 128x32, transposed
            int r = t >> 3, c = (t & 7) << 2;
            float4 a = *(const float4*)(X + (size_t)(m0 + r) * HID + k0 + c);
            As[c + 0][r] = a.x; As[c + 1][r] = a.y; As[c + 2][r] = a.z; As[c + 3][r] = a.w;
        }
#pragma unroll
        for (int t = tid; t < 512; t += 256) {         // W tile 32x64
            int r = t >> 4, c = (t & 15) << 2;
            *(float4*)&Bs[r][c] = *(const float4*)(W + (size_t)(k0 + r) * HD + c);
        }
        __syncthreads();
#pragma unroll
        for (int kk = 0; kk < 32; kk++) {
            ulonglong2 a01 = *(const ulonglong2*)&As[kk][ty * 8];
            ulonglong2 a23 = *(const ulonglong2*)&As[kk][ty * 8 + 4];
            float4 bv = *(const float4*)&Bs[kk][tx * 4];
            ull B0, B1, B2, B3;
            PACK2(B0, bv.x); PACK2(B1, bv.y); PACK2(B2, bv.z); PACK2(B3, bv.w);
            FMA2(acc[0][0], a01.x, B0); FMA2(acc[0][1], a01.x, B1);
            FMA2(acc[0][2], a01.x, B2); FMA2(acc[0][3], a01.x, B3);
            FMA2(acc[1][0], a01.y, B0); FMA2(acc[1][1], a01.y, B1);
            FMA2(acc[1][2], a01.y, B2); FMA2(acc[1][3], a01.y, B3);
            FMA2(acc[2][0], a23.x, B0); FMA2(acc[2][1], a23.x, B1);
            FMA2(acc[2][2], a23.x, B2); FMA2(acc[2][3], a23.x, B3);
            FMA2(acc[3][0], a23.y, B0); FMA2(acc[3][1], a23.y, B1);
            FMA2(acc[3][2], a23.y, B2); FMA2(acc[3][3], a23.y, B3);
        }
    }
    float4 bias = *(const float4*)(Bb + tx * 4);
#pragma unroll
    for (int p = 0; p < 4; p++) {
        float lo[4], hi[4];
        UNPK2(lo[0], hi[0], acc[p][0]); UNPK2(lo[1], hi[1], acc[p][1]);
        UNPK2(lo[2], hi[2], acc[p][2]); UNPK2(lo[3], hi[3], acc[p][3]);
        int r0 = m0 + ty * 8 + 2 * p;
        *(float4*)(O + (size_t)r0 * HD + tx * 4) =
            make_float4(lo[0] + bias.x, lo[1] + bias.y, lo[2] + bias.z, lo[3] + bias.w);
        *(float4*)(O + (size_t)(r0 + 1) * HD + tx * 4) =
            make_float4(hi[0] + bias.x, hi[1] + bias.y, hi[2] + bias.z, hi[3] + bias.w);
    }
}

// ---------------- scores + LayerNorm stats ----------------------------------
// One block owns 64 query rows and sweeps the full key range (j: 0..2048 in
// tiles of 128, d split in halves of 32). Emits raw scores + per-row mean/isig.
// grid (32, NB), 256 threads; per thread 4 rows x 8 cols (pairs along j).
__global__ __launch_bounds__(256) void k_scores() {
    __shared__ __align__(16) float Qs[64][68];    // [d][i]
    __shared__ __align__(16) float Ks[32][132];   // [d-half][j]

    const int b = blockIdx.y;
    const float* Q = g_q + (size_t)b * SEQ * HD;
    const float* K = g_k + (size_t)b * SEQ * HD;
    float*       C = g_sc + (size_t)b * SEQ * SEQ;

    const int i0 = blockIdx.x * 64;
    const int tid = threadIdx.x, tx = tid & 15, ty = tid >> 4;

#pragma unroll
    for (int t = tid; t < 1024; t += 256) {            // Q strip 64x64, transposed
        int r = t >> 4, c = (t & 15) << 2;
        float4 a = *(const float4*)(Q + (size_t)(i0 + r) * HD + c);
        Qs[c + 0][r] = a.x; Qs[c + 1][r] = a.y; Qs[c + 2][r] = a.z; Qs[c + 3][r] = a.w;
    }

    float rs1[4] = {}, rs2[4] = {};

    for (int j0 = 0; j0 < SEQ; j0 += 128) {
        ull acc[4][4] = {};   // [i][j-pair]
        for (int kh = 0; kh < HD; kh += 32) {
            __syncthreads();
#pragma unroll
            for (int t = tid; t < 1024; t += 256) {    // K tile 128x32, transposed
                int r = t >> 3, c = (t & 7) << 2;
                float4 a = *(const float4*)(K + (size_t)(j0 + r) * HD + kh + c);
                Ks[c + 0][r] = a.x; Ks[c + 1][r] = a.y; Ks[c + 2][r] = a.z; Ks[c + 3][r] = a.w;
            }
            __syncthreads();
#pragma unroll
            for (int kk = 0; kk < 32; kk++) {
                ulonglong2 b01 = *(const ulonglong2*)&Ks[kk][tx * 8];
                ulonglong2 b23 = *(const ulonglong2*)&Ks[kk][tx * 8 + 4];
                float4 av = *(const float4*)&Qs[kh + kk][ty * 4];
                ull A0, A1, A2, A3;
                PACK2(A0, av.x); PACK2(A1, av.y); PACK2(A2, av.z); PACK2(A3, av.w);
                FMA2(acc[0][0], A0, b01.x); FMA2(acc[0][1], A0, b01.y);
                FMA2(acc[0][2], A0, b23.x); FMA2(acc[0][3], A0, b23.y);
                FMA2(acc[1][0], A1, b01.x); FMA2(acc[1][1], A1, b01.y);
                FMA2(acc[1][2], A1, b23.x); FMA2(acc[1][3], A1, b23.y);
                FMA2(acc[2][0], A2, b01.x); FMA2(acc[2][1], A2, b01.y);
                FMA2(acc[2][2], A2, b23.x); FMA2(acc[2][3], A2, b23.y);
                FMA2(acc[3][0], A3, b01.x); FMA2(acc[3][1], A3, b01.y);
                FMA2(acc[3][2], A3, b23.x); FMA2(acc[3][3], A3, b23.y);
            }
        }
        // epilogue: write raw scores + accumulate row stats
#pragma unroll
        for (int i = 0; i < 4; i++) {
            float v[8];
            UNPK2(v[0], v[1], acc[i][0]); UNPK2(v[2], v[3], acc[i][1]);
            UNPK2(v[4], v[5], acc[i][2]); UNPK2(v[6], v[7], acc[i][3]);
            float s1 = 0.f, s2 = 0.f;
#pragma unroll
            for (int j = 0; j < 8; j++) { s1 += v[j]; s2 += v[j] * v[j]; }
            rs1[i] += s1; rs2[i] += s2;
            float* cp = C + (size_t)(i0 + ty * 4 + i) * SEQ + j0 + tx * 8;
            *(float4*)(cp)     = make_float4(v[0], v[1], v[2], v[3]);
            *(float4*)(cp + 4) = make_float4(v[4], v[5], v[6], v[7]);
        }
    }
    // reduce stats across the 16 tx lanes (lanes 0-15 / 16-31 of each warp)
#pragma unroll
    for (int i = 0; i < 4; i++) {
#pragma unroll
        for (int o = 8; o; o >>= 1) {
            rs1[i] += __shfl_xor_sync(0xffffffffu, rs1[i], o);
            rs2[i] += __shfl_xor_sync(0xffffffffu, rs2[i], o);
        }
    }
    if (tx == 0) {
#pragma unroll
        for (int i = 0; i < 4; i++) {
            int row = i0 + ty * 4 + i;
            float s1 = rs1[i] * INV32, s2 = rs2[i] * (INV32 * INV32);
            float mean = s1 * (1.f / 2048.f);
            float var  = (s2 - s1 * mean) * (1.f / 2047.f);
            float isig = 1.f / (sqrtf(var) + 1e-8f);
            g_mean[b * SEQ + row] = mean;
            g_isig[b * SEQ + row] = isig;
        }
    }
}

// ---------------- attn @ V with fused normalize+exp, split-K ----------------
// grid (16, KS, NB), BM=128, 256 threads, 8x4 per thread (pairs along M).
__global__ __launch_bounds__(256) void k_attnv() {
    __shared__ __align__(16) float Es[32][132];  // [k][i] exp'd probs (unnormalized)
    __shared__ __align__(16) float Vs[32][68];   // [k][d]

    const int b = blockIdx.z, ks = blockIdx.y;
    const float* E = g_sc + (size_t)b * SEQ * SEQ;
    const float* V = g_v  + (size_t)b * SEQ * HD;

    const int i0 = blockIdx.x * 128;
    const int kbeg = ks * (SEQ / KS);
    const int tid = threadIdx.x, tx = tid & 15, ty = tid >> 4;

    // per-thread fixed load rows: r = (tid>>3) + 32*it
    float al[4], be[4];
#pragma unroll
    for (int it = 0; it < 4; it++) {
        int row = b * SEQ + i0 + (tid >> 3) + 32 * it;
        float is = g_isig[row];
        al[it] = INV32 * is;
        be[it] = -g_mean[row] * is;
    }
    float ps[4] = {};
    ull acc[4][4] = {};   // [i-pair][d]

    for (int k0 = kbeg; k0 < kbeg + SEQ / KS; k0 += 32) {
        __syncthreads();
#pragma unroll
        for (int it = 0; it < 4; it++) {               // E tile 128x32 with exp
            int t = tid + it * 256;
            int r = t >> 3, c = (t & 7) << 2;
            float4 a = *(const float4*)(E + (size_t)(i0 + r) * SEQ + k0 + c);
            float e0 = __expf(fmaf(a.x, al[it], be[it]));
            float e1 = __expf(fmaf(a.y, al[it], be[it]));
            float e2 = __expf(fmaf(a.z, al[it], be[it]));
            float e3 = __expf(fmaf(a.w, al[it], be[it]));
            Es[c + 0][r] = e0; Es[c + 1][r] = e1; Es[c + 2][r] = e2; Es[c + 3][r] = e3;
            ps[it] += (e0 + e1) + (e2 + e3);
        }
#pragma unroll
        for (int t = tid; t < 512; t += 256) {         // V tile 32x64
            int r = t >> 4, c = (t & 15) << 2;
            *(float4*)&Vs[r][c] = *(const float4*)(V + (size_t)(k0 + r) * HD + c);
        }
        __syncthreads();
#pragma unroll
        for (int kk = 0; kk < 32; kk++) {
            ulonglong2 a01 = *(const ulonglong2*)&Es[kk][ty * 8];
            ulonglong2 a23 = *(const ulonglong2*)&Es[kk][ty * 8 + 4];
            float4 bv = *(const float4*)&Vs[kk][tx * 4];
            ull B0, B1, B2, B3;
            PACK2(B0, bv.x); PACK2(B1, bv.y); PACK2(B2, bv.z); PACK2(B3, bv.w);
            FMA2(acc[0][0], a01.x, B0); FMA2(acc[0][1], a01.x, B1);
            FMA2(acc[0][2], a01.x, B2); FMA2(acc[0][3], a01.x, B3);
            FMA2(acc[1][0], a01.y, B0); FMA2(acc[1][1], a01.y, B1);
            FMA2(acc[1][2], a01.y, B2); FMA2(acc[1][3], a01.y, B3);
            FMA2(acc[2][0], a23.x, B0); FMA2(acc[2][1], a23.x, B1);
            FMA2(acc[2][2], a23.x, B2); FMA2(acc[2][3], a23.x, B3);
            FMA2(acc[3][0], a23.y, B0); FMA2(acc[3][1], a23.y, B1);
            FMA2(acc[3][2], a23.y, B2); FMA2(acc[3][3], a23.y, B3);
        }
    }
    // partial expsums: reduce across the 8 lanes sharing each row
#pragma unroll
    for (int it = 0; it < 4; it++) {
#pragma unroll
        for (int o = 4; o; o >>= 1) ps[it] += __shfl_xor_sync(0xffffffffu, ps[it], o);
    }
    if ((tid & 7) == 0) {
#pragma unroll
        for (int it = 0; it < 4; it++)
            g_esp[ks][b * SEQ + i0 + (tid >> 3) + 32 * it] = ps[it];
    }
    // write partial head
    float* O = &g_hp[ks][(size_t)b * SEQ * HD];
#pragma unroll
    for (int p = 0; p < 4; p++) {
        float lo[4], hi[4];
        UNPK2(lo[0], hi[0], acc[p][0]); UNPK2(lo[1], hi[1], acc[p][1]);
        UNPK2(lo[2], hi[2], acc[p][2]); UNPK2(lo[3], hi[3], acc[p][3]);
        int r0 = i0 + ty * 8 + 2 * p;
        *(float4*)(O + (size_t)r0 * HD + tx * 4)       = make_float4(lo[0], lo[1], lo[2], lo[3]);
        *(float4*)(O + (size_t)(r0 + 1) * HD + tx * 4) = make_float4(hi[0], hi[1], hi[2], hi[3]);
    }
}

// ---------------- reduce split-K partials, apply 1/sum(exp) -----------------
__global__ __launch_bounds__(256) void k_hred() {
    int idx = blockIdx.x * 256 + threadIdx.x;
    int row = idx >> 6;
    float tot = (g_esp[0][row] + g_esp[1][row]) + (g_esp[2][row] + g_esp[3][row]);
    float s = (g_hp[0][idx] + g_hp[1][idx]) + (g_hp[2][idx] + g_hp[3][idx]);
    g_head[idx] = s * (1.f / tot);
}

// ---------------- out = head @ Wfold + bout  (M=8192, N=1024, K=64) ----------
// BM=128, BN=64, grid (16, 64), 8x4 per thread (pairs along M).
__global__ __launch_bounds__(256) void k_final(float* __restrict__ out,
                                               const float* __restrict__ bout) {
    __shared__ __align__(16) float As[32][132];
    __shared__ __align__(16) float Bs[32][68];

    const int m0 = blockIdx.y * 128, j0 = blockIdx.x * 64;
    const int tid = threadIdx.x, tx = tid & 15, ty = tid >> 4;
    ull acc[4][4] = {};

    for (int k0 = 0; k0 < HD; k0 += 32) {
        __syncthreads();
#pragma unroll
        for (int t = tid; t < 1024; t += 256) {
            int r = t >> 3, c = (t & 7) << 2;
            float4 a = *(const float4*)(g_head + (size_t)(m0 + r) * HD + k0 + c);
            As[c + 0][r] = a.x; As[c + 1][r] = a.y; As[c + 2][r] = a.z; As[c + 3][r] = a.w;
        }
#pragma unroll
        for (int t = tid; t < 512; t += 256) {
            int r = t >> 4, c = (t & 15) << 2;
            *(float4*)&Bs[r][c] = *(const float4*)(g_wf + (size_t)(k0 + r) * HID + j0 + c);
        }
        __syncthreads();
#pragma unroll
        for (int kk = 0; kk < 32; kk++) {
            ulonglong2 a01 = *(const ulonglong2*)&As[kk][ty * 8];
            ulonglong2 a23 = *(const ulonglong2*)&As[kk][ty * 8 + 4];
            float4 bv = *(const float4*)&Bs[kk][tx * 4];
            ull B0, B1, B2, B3;
            PACK2(B0, bv.x); PACK2(B1, bv.y); PACK2(B2, bv.z); PACK2(B3, bv.w);
            FMA2(acc[0][0], a01.x, B0); FMA2(acc[0][1], a01.x, B1);
            FMA2(acc[0][2], a01.x, B2); FMA2(acc[0][3], a01.x, B3);
            FMA2(acc[1][0], a01.y, B0); FMA2(acc[1][1], a01.y, B1);
            FMA2(acc[1][2], a01.y, B2); FMA2(acc[1][3], a01.y, B3);
            FMA2(acc[2][0], a23.x, B0); FMA2(acc[2][1], a23.x, B1);
            FMA2(acc[2][2], a23.x, B2); FMA2(acc[2][3], a23.x, B3);
            FMA2(acc[3][0], a23.y, B0); FMA2(acc[3][1], a23.y, B1);
            FMA2(acc[3][2], a23.y, B2); FMA2(acc[3][3], a23.y, B3);
        }
    }
    float4 bias = *(const float4*)(bout + j0 + tx * 4);
#pragma unroll
    for (int p = 0; p < 4; p++) {
        float lo[4], hi[4];
        UNPK2(lo[0], hi[0], acc[p][0]); UNPK2(lo[1], hi[1], acc[p][1]);
        UNPK2(lo[2], hi[2], acc[p][2]); UNPK2(lo[3], hi[3], acc[p][3]);
        int r0 = m0 + ty * 8 + 2 * p;
        *(float4*)(out + (size_t)r0 * HID + j0 + tx * 4) =
            make_float4(lo[0] + bias.x, lo[1] + bias.y, lo[2] + bias.z, lo[3] + bias.w);
        *(float4*)(out + (size_t)(r0 + 1) * HID + j0 + tx * 4) =
            make_float4(hi[0] + bias.x, hi[1] + bias.y, hi[2] + bias.z, hi[3] + bias.w);
    }
}

// ---------------------------------------------------------------------------
extern "C" void kernel_launch(void* const* d_in, const int* in_sizes, int n_in,
                              void* d_out, int out_size) {
    const float* query = (const float*)d_in[0];
    const float* key   = (const float*)d_in[1];
    const float* value = (const float*)d_in[2];
    // d_in[3] = mask: adding -1e-32 is a float32 no-op -> ignored
    const float* Wq    = (const float*)d_in[4];
    const float* bq    = (const float*)d_in[5];
    const float* Wk    = (const float*)d_in[6];
    const float* bk    = (const float*)d_in[7];
    const float* Wv    = (const float*)d_in[8];
    const float* bv    = (const float*)d_in[9];
    const float* Wout  = (const float*)d_in[10];
    const float* bout  = (const float*)d_in[11];
    // d_in[12] = seq_mask (0) -> ignored
    float* out = (float*)d_out;

    k_wfold<<<256, 256>>>(Wout);
    k_proj<<<dim3(64, 3), 256>>>(query, key, value, Wq, Wk, Wv, bq, bk, bv);
    k_scores<<<dim3(32, NB), 256>>>();
    k_attnv<<<dim3(16, KS, NB), 256>>>();
    k_hred<<<(NB * SEQ * HD) / 256, 256>>>();
    k_final<<<dim3(16, 64), 256>>>(out, bout);
}

// round 10
// speedup vs baseline: 1.2493x; 1.2493x over previous
#include <cuda_runtime.h>
#include <cuda_bf16.h>
#include <stdint.h>

#define NB   4
#define SEQ  2048
#define HID  1024
#define HD   64
#define NH   16
#define KS   8       // split-K for attn@V
#define NT   16      // j-tiles for scores (2048/128)
#define NST  32      // stat partials = NT * 2 warp-cols
#define INV32 0.03125f

typedef unsigned long long ull;

// ---------------- packed f32x2 helpers (proj/final SIMT path) ---------------
#define FMA2(acc, a, b) asm("fma.rn.f32x2 %0, %1, %2, %0;" : "+l"(acc) : "l"(a), "l"(b))
#define PACK2(d, s)     asm("mov.b64 %0, {%1, %1};" : "=l"(d) : "f"(s))
#define UNPK2(lo, hi, v) asm("mov.b64 {%0, %1}, %2;" : "=f"(lo), "=f"(hi) : "l"(v))

// ---------------- base-target tensor-core helpers (NO tcgen05!) -------------
__device__ __forceinline__ uint32_t smem_u32(const void* p) {
    uint32_t a;
    asm("{ .reg .u64 t; cvta.to.shared.u64 t, %1; cvt.u32.u64 %0, t; }" : "=r"(a) : "l"(p));
    return a;
}
#define SW128(o) ((o) ^ (((o) >> 3) & 0x70))

__device__ __forceinline__ void ldsm_x4(uint32_t r[4], uint32_t addr) {
    asm volatile("ldmatrix.sync.aligned.m8n8.x4.shared.b16 {%0,%1,%2,%3}, [%4];"
                 : "=r"(r[0]), "=r"(r[1]), "=r"(r[2]), "=r"(r[3]) : "r"(addr));
}
#define MMA16816(c, a, b0, b1) \
    asm volatile("mma.sync.aligned.m16n8k16.row.col.f32.bf16.bf16.f32 " \
        "{%0,%1,%2,%3}, {%4,%5,%6,%7}, {%8,%9}, {%0,%1,%2,%3};" \
        : "+f"((c)[0]), "+f"((c)[1]), "+f"((c)[2]), "+f"((c)[3]) \
        : "r"((a)[0]), "r"((a)[1]), "r"((a)[2]), "r"((a)[3]), "r"(b0), "r"(b1))

// A-fragment ldmatrix address: rows m0..m0+15, k-bytes kb0 / kb0+16
__device__ __forceinline__ uint32_t a_addr(uint32_t base, int lane, int m0, int kb0) {
    int row = m0 + (lane & 15);
    int kb  = kb0 + ((lane >> 4) << 4);
    return base + SW128(row * 128 + kb);
}
// B-fragment x4 (covers n-tiles n0 and n0+8, both k halves)
__device__ __forceinline__ uint32_t b_addr(uint32_t base, int lane, int n0, int kb0) {
    int n  = n0 + (lane & 7) + ((lane >> 4) << 3);
    int kb = kb0 + ((lane & 8) ? 16 : 0);
    return base + SW128(n * 128 + kb);
}

// ---------------- scratch ---------------------------------------------------
static __device__ float g_q[NB * SEQ * HD];
static __device__ float g_k[NB * SEQ * HD];
static __device__ float g_v[NB * SEQ * HD];
static __device__ __nv_bfloat16 g_qh[NB * SEQ * HD], g_ql[NB * SEQ * HD];
static __device__ __nv_bfloat16 g_kh[NB * SEQ * HD], g_kl[NB * SEQ * HD];
static __device__ __nv_bfloat16 g_vth[NB * HD * SEQ], g_vtl[NB * HD * SEQ];  // [b][d][k]
static __device__ float g_sc[(size_t)NB * SEQ * SEQ];       // raw scores
static __device__ float g_s1[NST][NB * SEQ], g_s2[NST][NB * SEQ];
static __device__ float g_mean[NB * SEQ], g_isig[NB * SEQ];
static __device__ float g_esp[KS][NB * SEQ];
static __device__ float g_hp[KS][NB * SEQ * HD];
static __device__ float g_head[NB * SEQ * HD];
static __device__ float g_wf[HD * HID];

// ---------------- Wfold ------------------------------------------------------
__global__ __launch_bounds__(256) void k_wfold(const float* __restrict__ Wout) {
    int idx = blockIdx.x * 256 + threadIdx.x;
    if (idx >= HD * HID) return;
    int d = idx >> 10, j = idx & 1023;
    float s = 0.f;
#pragma unroll
    for (int h = 0; h < NH; h++) s += Wout[(h * HD + d) * HID + j];
    g_wf[idx] = s;
}

// ---------------- projections (SIMT f32x2, measured-working) -----------------
__global__ __launch_bounds__(256) void k_proj(
    const float* __restrict__ Xq, const float* __restrict__ Xk, const float* __restrict__ Xv,
    const float* __restrict__ Wq, const float* __restrict__ Wk, const float* __restrict__ Wv,
    const float* __restrict__ Bq, const float* __restrict__ Bk, const float* __restrict__ Bv)
{
    __shared__ __align__(16) float As[32][132];
    __shared__ __align__(16) float Bs[32][68];

    const int which = blockIdx.y;
    const float* X  = (which == 0) ? Xq : (which == 1) ? Xk : Xv;
    const float* W  = (which == 0) ? Wq : (which == 1) ? Wk : Wv;
    const float* Bb = (which == 0) ? Bq : (which == 1) ? Bk : Bv;
    float*       O  = (which == 0) ? g_q : (which == 1) ? g_k : g_v;

    const int m0 = blockIdx.x * 128;
    const int tid = threadIdx.x, tx = tid & 15, ty = tid >> 4;
    ull acc[4][4] = {};

    for (int k0 = 0; k0 < HID; k0 += 32) {
        __syncthreads();
#pragma unroll
        for (int t = tid; t < 1024; t += 256) {
            int r = t >> 3, c = (t & 7) << 2;
            float4 a = *(const float4*)(X + (size_t)(m0 + r) * HID + k0 + c);
            As[c + 0][r] = a.x; As[c + 1][r] = a.y; As[c + 2][r] = a.z; As[c + 3][r] = a.w;
        }
#pragma unroll
        for (int t = tid; t < 512; t += 256) {
            int r = t >> 4, c = (t & 15) << 2;
            *(float4*)&Bs[r][c] = *(const float4*)(W + (size_t)(k0 + r) * HD + c);
        }
        __syncthreads();
#pragma unroll
        for (int kk = 0; kk < 32; kk++) {
            ulonglong2 a01 = *(const ulonglong2*)&As[kk][ty * 8];
            ulonglong2 a23 = *(const ulonglong2*)&As[kk][ty * 8 + 4];
            float4 bv = *(const float4*)&Bs[kk][tx * 4];
            ull B0, B1, B2, B3;
            PACK2(B0, bv.x); PACK2(B1, bv.y); PACK2(B2, bv.z); PACK2(B3, bv.w);
            FMA2(acc[0][0], a01.x, B0); FMA2(acc[0][1], a01.x, B1);
            FMA2(acc[0][2], a01.x, B2); FMA2(acc[0][3], a01.x, B3);
            FMA2(acc[1][0], a01.y, B0); FMA2(acc[1][1], a01.y, B1);
            FMA2(acc[1][2], a01.y, B2); FMA2(acc[1][3], a01.y, B3);
            FMA2(acc[2][0], a23.x, B0); FMA2(acc[2][1], a23.x, B1);
            FMA2(acc[2][2], a23.x, B2); FMA2(acc[2][3], a23.x, B3);
            FMA2(acc[3][0], a23.y, B0); FMA2(acc[3][1], a23.y, B1);
            FMA2(acc[3][2], a23.y, B2); FMA2(acc[3][3], a23.y, B3);
        }
    }
    float4 bias = *(const float4*)(Bb + tx * 4);
#pragma unroll
    for (int p = 0; p < 4; p++) {
        float lo[4], hi[4];
        UNPK2(lo[0], hi[0], acc[p][0]); UNPK2(lo[1], hi[1], acc[p][1]);
        UNPK2(lo[2], hi[2], acc[p][2]); UNPK2(lo[3], hi[3], acc[p][3]);
        int r0 = m0 + ty * 8 + 2 * p;
        *(float4*)(O + (size_t)r0 * HD + tx * 4) =
            make_float4(lo[0] + bias.x, lo[1] + bias.y, lo[2] + bias.z, lo[3] + bias.w);
        *(float4*)(O + (size_t)(r0 + 1) * HD + tx * 4) =
            make_float4(hi[0] + bias.x, hi[1] + bias.y, hi[2] + bias.z, hi[3] + bias.w);
    }
}

// ---------------- split fp32 -> bf16 hi/lo (q, k straight; v transposed) -----
__global__ __launch_bounds__(256) void k_split() {
    const int job = blockIdx.y;
    int i4 = blockIdx.x * 256 + threadIdx.x;           // 131072 float4-units
    if (job < 2) {
        const float* S = job ? g_k : g_q;
        __nv_bfloat16* H = job ? g_kh : g_qh;
        __nv_bfloat16* L = job ? g_kl : g_ql;
        float4 x = ((const float4*)S)[i4];
        float xs[4] = {x.x, x.y, x.z, x.w};
        __nv_bfloat16 h[4], l[4];
#pragma unroll
        for (int i = 0; i < 4; i++) {
            h[i] = __float2bfloat16(xs[i]);
            l[i] = __float2bfloat16(xs[i] - __bfloat162float(h[i]));
        }
        size_t base = (size_t)i4 * 4;
        *(__nv_bfloat162*)(H + base)     = __nv_bfloat162(h[0], h[1]);
        *(__nv_bfloat162*)(H + base + 2) = __nv_bfloat162(h[2], h[3]);
        *(__nv_bfloat162*)(L + base)     = __nv_bfloat162(l[0], l[1]);
        *(__nv_bfloat162*)(L + base + 2) = __nv_bfloat162(l[2], l[3]);
    } else {
        // transpose V: out[b][d][k] = V[b][k][d]
        int kq = i4 & 511, bd = i4 >> 9;               // bd in [0,256)
        int b = bd >> 6, d = bd & 63, k0 = kq * 4;
        __nv_bfloat16 h[4], l[4];
#pragma unroll
        for (int i = 0; i < 4; i++) {
            float x = g_v[((size_t)(b * SEQ + k0 + i)) * HD + d];
            h[i] = __float2bfloat16(x);
            l[i] = __float2bfloat16(x - __bfloat162float(h[i]));
        }
        size_t base = (size_t)bd * SEQ + k0;
        *(__nv_bfloat162*)(g_vth + base)     = __nv_bfloat162(h[0], h[1]);
        *(__nv_bfloat162*)(g_vth + base + 2) = __nv_bfloat162(h[2], h[3]);
        *(__nv_bfloat162*)(g_vtl + base)     = __nv_bfloat162(l[0], l[1]);
        *(__nv_bfloat162*)(g_vtl + base + 2) = __nv_bfloat162(l[2], l[3]);
    }
}

// ---------------- scores via mma.sync bf16 3-term + partial LN stats ---------
// block tile 128x128, 8 warps (4x2), warp tile 32x64. grid (NT, 16, NB).
__global__ __launch_bounds__(256) void k_scores_mma() {
    extern __shared__ __align__(1024) char smem[];
    const int QH = 0, QL = 16384, KH = 32768, KL = 49152;
    const uint32_t sb = smem_u32(smem);
    const int tid = threadIdx.x, w = tid >> 5, lane = tid & 31;
    const int wm = w >> 1, wn = w & 1;
    const int nt = blockIdx.x, mt = blockIdx.y, b = blockIdx.z;
    const int i0 = mt * 128, j0 = nt * 128;
    const size_t qr0 = (size_t)b * SEQ + i0, kr0 = (size_t)b * SEQ + j0;

    // fill tiles: 128 rows x 64 bf16 (128B rows, SW128 swizzle)
    for (int idx = tid; idx < 1024; idx += 256) {
        int r = idx >> 3, c = idx & 7;
        uint32_t so = SW128(r * 128 + c * 16);
        *(uint4*)(smem + QH + so) = ((const uint4*)(g_qh + (qr0 + r) * HD))[c];
        *(uint4*)(smem + QL + so) = ((const uint4*)(g_ql + (qr0 + r) * HD))[c];
        *(uint4*)(smem + KH + so) = ((const uint4*)(g_kh + (kr0 + r) * HD))[c];
        *(uint4*)(smem + KL + so) = ((const uint4*)(g_kl + (kr0 + r) * HD))[c];
    }
    __syncthreads();

    float c[2][8][4] = {};
    const int TA[3] = {QH, QL, QH}, TB[3] = {KH, KH, KL};
#pragma unroll
    for (int t = 0; t < 3; t++) {
        uint32_t ab = sb + TA[t], bb = sb + TB[t];
#pragma unroll
        for (int k16 = 0; k16 < 4; k16++) {
            int kb0 = k16 * 32;
            uint32_t a[2][4];
            ldsm_x4(a[0], a_addr(ab, lane, wm * 32, kb0));
            ldsm_x4(a[1], a_addr(ab, lane, wm * 32 + 16, kb0));
#pragma unroll
            for (int nj = 0; nj < 4; nj++) {
                uint32_t r[4];
                ldsm_x4(r, b_addr(bb, lane, wn * 64 + nj * 16, kb0));
                MMA16816(c[0][2 * nj],     a[0], r[0], r[1]);
                MMA16816(c[0][2 * nj + 1], a[0], r[2], r[3]);
                MMA16816(c[1][2 * nj],     a[1], r[0], r[1]);
                MMA16816(c[1][2 * nj + 1], a[1], r[2], r[3]);
            }
        }
    }

    // epilogue: write raw scores + per-row partial stats
    const int q = lane >> 2, cpair = (lane & 3) * 2;
    float s1v[4] = {}, s2v[4] = {};
    float* Cb = g_sc + (size_t)b * SEQ * SEQ;
#pragma unroll
    for (int mi = 0; mi < 2; mi++) {
        int row0 = i0 + wm * 32 + mi * 16 + q;
#pragma unroll
        for (int ni = 0; ni < 8; ni++) {
            float* c4 = c[mi][ni];
            int col = j0 + wn * 64 + ni * 8 + cpair;
            *(float2*)(Cb + (size_t)row0 * SEQ + col)       = make_float2(c4[0], c4[1]);
            *(float2*)(Cb + (size_t)(row0 + 8) * SEQ + col) = make_float2(c4[2], c4[3]);
            s1v[mi * 2 + 0] += c4[0] + c4[1];
            s2v[mi * 2 + 0] += c4[0] * c4[0] + c4[1] * c4[1];
            s1v[mi * 2 + 1] += c4[2] + c4[3];
            s2v[mi * 2 + 1] += c4[2] * c4[2] + c4[3] * c4[3];
        }
    }
#pragma unroll
    for (int j = 0; j < 4; j++) {
        s1v[j] += __shfl_xor_sync(0xffffffffu, s1v[j], 1);
        s2v[j] += __shfl_xor_sync(0xffffffffu, s2v[j], 1);
        s1v[j] += __shfl_xor_sync(0xffffffffu, s1v[j], 2);
        s2v[j] += __shfl_xor_sync(0xffffffffu, s2v[j], 2);
    }
    if ((lane & 3) == 0) {
        const int sidx = nt * 2 + wn;
#pragma unroll
        for (int j = 0; j < 4; j++) {
            int mi = j >> 1, sub = j & 1;
            int row = i0 + wm * 32 + mi * 16 + sub * 8 + q;
            g_s1[sidx][b * SEQ + row] = s1v[j];
            g_s2[sidx][b * SEQ + row] = s2v[j];
        }
    }
}

// ---------------- reduce stats -> mean/isig ----------------------------------
__global__ __launch_bounds__(256) void k_stats() {
    int r = blockIdx.x * 256 + threadIdx.x;      // 8192 rows
    float s1 = 0.f, s2 = 0.f;
#pragma unroll
    for (int t = 0; t < NST; t++) { s1 += g_s1[t][r]; s2 += g_s2[t][r]; }
    float s1s = s1 * INV32, s2s = s2 * (INV32 * INV32);
    float mean = s1s * (1.f / 2048.f);
    float var  = (s2s - s1s * mean) * (1.f / 2047.f);
    g_mean[r] = mean;
    g_isig[r] = 1.f / (sqrtf(var) + 1e-8f);
}

// ---------------- attn@V via mma.sync, fused exp, split-K --------------------
// block M=128 x N=64, 8 warps (16 rows each). grid (16, KS, NB), 256 threads.
__global__ __launch_bounds__(256) void k_attnv_mma() {
    extern __shared__ __align__(1024) char smem[];
    const int PH = 0, PL = 16384, VH = 32768, VL = 40960;
    const uint32_t sb = smem_u32(smem);
    const int tid = threadIdx.x, w = tid >> 5, lane = tid & 31;
    const int mt = blockIdx.x, ks = blockIdx.y, b = blockIdx.z;
    const int i0 = mt * 128, kbeg = ks * (SEQ / KS);

    float al = 0.f, be = 0.f, ps = 0.f;
    const float* Erow = nullptr;
    if (tid < 128) {
        int rowg = b * SEQ + i0 + tid;
        float is = g_isig[rowg];
        al = INV32 * is;
        be = -g_mean[rowg] * is;
        Erow = g_sc + (size_t)b * SEQ * SEQ + (size_t)(i0 + tid) * SEQ;
    }
    float c[8][4] = {};

    for (int st = 0; st < 4; st++) {                    // 4 subtiles of k=64
        const int k0 = kbeg + st * 64;
        if (st) __syncthreads();
        if (tid < 128) {
            // P tile: one row per thread, exp + hi/lo split
            const float4* E4 = (const float4*)(Erow + k0);
#pragma unroll
            for (int cc = 0; cc < 16; cc++) {
                float4 sv = E4[cc];
                float e0 = __expf(fmaf(sv.x, al, be));
                float e1 = __expf(fmaf(sv.y, al, be));
                float e2 = __expf(fmaf(sv.z, al, be));
                float e3 = __expf(fmaf(sv.w, al, be));
                ps += (e0 + e1) + (e2 + e3);
                __nv_bfloat16 h0 = __float2bfloat16(e0), h1 = __float2bfloat16(e1);
                __nv_bfloat16 h2 = __float2bfloat16(e2), h3 = __float2bfloat16(e3);
                __nv_bfloat16 l0 = __float2bfloat16(e0 - __bfloat162float(h0));
                __nv_bfloat16 l1 = __float2bfloat16(e1 - __bfloat162float(h1));
                __nv_bfloat16 l2 = __float2bfloat16(e2 - __bfloat162float(h2));
                __nv_bfloat16 l3 = __float2bfloat16(e3 - __bfloat162float(h3));
                uint32_t so = SW128(tid * 128 + cc * 8);
                *(__nv_bfloat162*)(smem + PH + so)     = __nv_bfloat162(h0, h1);
                *(__nv_bfloat162*)(smem + PH + so + 4) = __nv_bfloat162(h2, h3);
                *(__nv_bfloat162*)(smem + PL + so)     = __nv_bfloat162(l0, l1);
                *(__nv_bfloat162*)(smem + PL + so + 4) = __nv_bfloat162(l2, l3);
            }
        } else {
            // V^T tiles: 64 rows (d) x 64 cols (k), hi + lo
            int t2 = tid - 128;
            for (int idx = t2; idx < 512; idx += 128) {
                int r = idx >> 3, cc = idx & 7;
                uint32_t so = SW128(r * 128 + cc * 16);
                const uint4* sh = (const uint4*)(g_vth + ((size_t)(b * HD + r)) * SEQ + k0);
                const uint4* sl = (const uint4*)(g_vtl + ((size_t)(b * HD + r)) * SEQ + k0);
                *(uint4*)(smem + VH + so) = sh[cc];
                *(uint4*)(smem + VL + so) = sl[cc];
            }
        }
        __syncthreads();

        const int TA[3] = {PH, PL, PH}, TB[3] = {VH, VH, VL};
#pragma unroll
        for (int t = 0; t < 3; t++) {
            uint32_t ab = sb + TA[t], bb = sb + TB[t];
#pragma unroll
            for (int k16 = 0; k16 < 4; k16++) {
                int kb0 = k16 * 32;
                uint32_t a[4];
                ldsm_x4(a, a_addr(ab, lane, w * 16, kb0));
#pragma unroll
                for (int nj = 0; nj < 4; nj++) {
                    uint32_t r[4];
                    ldsm_x4(r, b_addr(bb, lane, nj * 16, kb0));
                    MMA16816(c[2 * nj],     a, r[0], r[1]);
                    MMA16816(c[2 * nj + 1], a, r[2], r[3]);
                }
            }
        }
    }

    if (tid < 128) g_esp[ks][b * SEQ + i0 + tid] = ps;

    // epilogue: write partial head [row][64]
    const int q = lane >> 2, cpair = (lane & 3) * 2;
    float* O = g_hp[ks] + ((size_t)(b * SEQ + i0 + w * 16)) * HD;
#pragma unroll
    for (int ni = 0; ni < 8; ni++) {
        int col = ni * 8 + cpair;
        *(float2*)(O + (size_t)q * HD + col)       = make_float2(c[ni][0], c[ni][1]);
        *(float2*)(O + (size_t)(q + 8) * HD + col) = make_float2(c[ni][2], c[ni][3]);
    }
}

// ---------------- reduce split-K partials, apply 1/sum(exp) ------------------
__global__ __launch_bounds__(256) void k_hred() {
    int idx = blockIdx.x * 256 + threadIdx.x;
    int row = idx >> 6;
    float tot = 0.f, s = 0.f;
#pragma unroll
    for (int t = 0; t < KS; t++) { tot += g_esp[t][row]; s += g_hp[t][idx]; }
    g_head[idx] = s * (1.f / tot);
}

// ---------------- out = head @ Wfold + bout (SIMT f32x2) ---------------------
__global__ __launch_bounds__(256) void k_final(float* __restrict__ out,
                                               const float* __restrict__ bout) {
    __shared__ __align__(16) float As[32][132];
    __shared__ __align__(16) float Bs[32][68];

    const int m0 = blockIdx.y * 128, j0 = blockIdx.x * 64;
    const int tid = threadIdx.x, tx = tid & 15, ty = tid >> 4;
    ull acc[4][4] = {};

    for (int k0 = 0; k0 < HD; k0 += 32) {
        __syncthreads();
#pragma unroll
        for (int t = tid; t < 1024; t += 256) {
            int r = t >> 3, c = (t & 7) << 2;
            float4 a = *(const float4*)(g_head + (size_t)(m0 + r) * HD + k0 + c);
            As[c + 0][r] = a.x; As[c + 1][r] = a.y; As[c + 2][r] = a.z; As[c + 3][r] = a.w;
        }
#pragma unroll
        for (int t = tid; t < 512; t += 256) {
            int r = t >> 4, c = (t & 15) << 2;
            *(float4*)&Bs[r][c] = *(const float4*)(g_wf + (size_t)(k0 + r) * HID + j0 + c);
        }
        __syncthreads();
#pragma unroll
        for (int kk = 0; kk < 32; kk++) {
            ulonglong2 a01 = *(const ulonglong2*)&As[kk][ty * 8];
            ulonglong2 a23 = *(const ulonglong2*)&As[kk][ty * 8 + 4];
            float4 bv = *(const float4*)&Bs[kk][tx * 4];
            ull B0, B1, B2, B3;
            PACK2(B0, bv.x); PACK2(B1, bv.y); PACK2(B2, bv.z); PACK2(B3, bv.w);
            FMA2(acc[0][0], a01.x, B0); FMA2(acc[0][1], a01.x, B1);
            FMA2(acc[0][2], a01.x, B2); FMA2(acc[0][3], a01.x, B3);
            FMA2(acc[1][0], a01.y, B0); FMA2(acc[1][1], a01.y, B1);
            FMA2(acc[1][2], a01.y, B2); FMA2(acc[1][3], a01.y, B3);
            FMA2(acc[2][0], a23.x, B0); FMA2(acc[2][1], a23.x, B1);
            FMA2(acc[2][2], a23.x, B2); FMA2(acc[2][3], a23.x, B3);
            FMA2(acc[3][0], a23.y, B0); FMA2(acc[3][1], a23.y, B1);
            FMA2(acc[3][2], a23.y, B2); FMA2(acc[3][3], a23.y, B3);
        }
    }
    float4 bias = *(const float4*)(bout + j0 + tx * 4);
#pragma unroll
    for (int p = 0; p < 4; p++) {
        float lo[4], hi[4];
        UNPK2(lo[0], hi[0], acc[p][0]); UNPK2(lo[1], hi[1], acc[p][1]);
        UNPK2(lo[2], hi[2], acc[p][2]); UNPK2(lo[3], hi[3], acc[p][3]);
        int r0 = m0 + ty * 8 + 2 * p;
        *(float4*)(out + (size_t)r0 * HID + j0 + tx * 4) =
            make_float4(lo[0] + bias.x, lo[1] + bias.y, lo[2] + bias.z, lo[3] + bias.w);
        *(float4*)(out + (size_t)(r0 + 1) * HID + j0 + tx * 4) =
            make_float4(hi[0] + bias.x, hi[1] + bias.y, hi[2] + bias.z, hi[3] + bias.w);
    }
}

// ---------------------------------------------------------------------------
extern "C" void kernel_launch(void* const* d_in, const int* in_sizes, int n_in,
                              void* d_out, int out_size) {
    const float* query = (const float*)d_in[0];
    const float* key   = (const float*)d_in[1];
    const float* value = (const float*)d_in[2];
    // d_in[3] = mask: adding -1e-32 is a float32 no-op -> ignored
    const float* Wq    = (const float*)d_in[4];
    const float* bq    = (const float*)d_in[5];
    const float* Wk    = (const float*)d_in[6];
    const float* bk    = (const float*)d_in[7];
    const float* Wv    = (const float*)d_in[8];
    const float* bv    = (const float*)d_in[9];
    const float* Wout  = (const float*)d_in[10];
    const float* bout  = (const float*)d_in[11];
    // d_in[12] = seq_mask (0) -> ignored
    float* out = (float*)d_out;

    cudaFuncSetAttribute(k_scores_mma, cudaFuncAttributeMaxDynamicSharedMemorySize, 65536);
    cudaFuncSetAttribute(k_attnv_mma,  cudaFuncAttributeMaxDynamicSharedMemorySize, 49152);

    k_wfold<<<256, 256>>>(Wout);
    k_proj<<<dim3(64, 3), 256>>>(query, key, value, Wq, Wk, Wv, bq, bk, bv);
    k_split<<<dim3(512, 3), 256>>>();
    k_scores_mma<<<dim3(NT, 16, NB), 256, 65536>>>();
    k_stats<<<NB * SEQ / 256, 256>>>();
    k_attnv_mma<<<dim3(16, KS, NB), 256, 49152>>>();
    k_hred<<<(NB * SEQ * HD) / 256, 256>>>();
    k_final<<<dim3(16, 64), 256>>>(out, bout);
}

// round 14
// speedup vs baseline: 1.3195x; 1.0562x over previous
#include <cuda_runtime.h>
#include <cuda_bf16.h>
#include <stdint.h>

#define NB   4
#define SEQ  2048
#define HID  1024
#define HD   64
#define NH   16
#define KS   8       // split-K for attn@V
#define NT   16      // j-tiles for scores (2048/128)
#define NST  32      // stat partials = NT * 2 warp-cols
#define INV32 0.03125f

typedef unsigned long long ull;

// ---------------- base-target tensor-core helpers (NO tcgen05) --------------
__device__ __forceinline__ uint32_t smem_u32(const void* p) {
    uint32_t a;
    asm("{ .reg .u64 t; cvta.to.shared.u64 t, %1; cvt.u32.u64 %0, t; }" : "=r"(a) : "l"(p));
    return a;
}
#define SW128(o) ((o) ^ (((o) >> 3) & 0x70))

__device__ __forceinline__ void ldsm_x4(uint32_t r[4], uint32_t addr) {
    asm volatile("ldmatrix.sync.aligned.m8n8.x4.shared.b16 {%0,%1,%2,%3}, [%4];"
                 : "=r"(r[0]), "=r"(r[1]), "=r"(r[2]), "=r"(r[3]) : "r"(addr));
}
#define MMA16816(c, a, b0, b1) \
    asm volatile("mma.sync.aligned.m16n8k16.row.col.f32.bf16.bf16.f32 " \
        "{%0,%1,%2,%3}, {%4,%5,%6,%7}, {%8,%9}, {%0,%1,%2,%3};" \
        : "+f"((c)[0]), "+f"((c)[1]), "+f"((c)[2]), "+f"((c)[3]) \
        : "r"((a)[0]), "r"((a)[1]), "r"((a)[2]), "r"((a)[3]), "r"(b0), "r"(b1))

__device__ __forceinline__ uint32_t a_addr(uint32_t base, int lane, int m0, int kb0) {
    int row = m0 + (lane & 15);
    int kb  = kb0 + ((lane >> 4) << 4);
    return base + SW128(row * 128 + kb);
}
__device__ __forceinline__ uint32_t b_addr(uint32_t base, int lane, int n0, int kb0) {
    int n  = n0 + (lane & 7) + ((lane >> 4) << 3);
    int kb = kb0 + ((lane & 8) ? 16 : 0);
    return base + SW128(n * 128 + kb);
}
__device__ __forceinline__ void split_bf16(float x, __nv_bfloat16& h, __nv_bfloat16& l) {
    h = __float2bfloat16(x);
    l = __float2bfloat16(x - __bfloat162float(h));
}

// ---------------- scratch ---------------------------------------------------
static __device__ float g_v[NB * SEQ * HD];
static __device__ __nv_bfloat16 g_qh[NB * SEQ * HD], g_ql[NB * SEQ * HD];
static __device__ __nv_bfloat16 g_kh[NB * SEQ * HD], g_kl[NB * SEQ * HD];
static __device__ __nv_bfloat16 g_vth[NB * HD * SEQ], g_vtl[NB * HD * SEQ];  // [b][d][k]
static __device__ __nv_bfloat16 g_wth[3][HD * HID], g_wtl[3][HD * HID];      // W^T [n][k]
static __device__ __nv_bfloat16 g_wfth[HID * HD], g_wftl[HID * HD];          // Wfold^T [j][d]
static __device__ float g_sc[(size_t)NB * SEQ * SEQ];
static __device__ float g_s1[NST][NB * SEQ], g_s2[NST][NB * SEQ];
static __device__ float g_mean[NB * SEQ], g_isig[NB * SEQ];
static __device__ float g_esp[KS][NB * SEQ];
static __device__ float g_hp[KS][NB * SEQ * HD];
static __device__ __nv_bfloat16 g_hh[NB * SEQ * HD], g_hl[NB * SEQ * HD];    // head hi/lo

// ---------------- weight prep: transpose + hi/lo split + Wfold ---------------
// grid (256, 4): jobs 0..2 = Wq/Wk/Wv -> [64][1024]; job 3 = Wfold^T -> [1024][64]
__global__ __launch_bounds__(256) void k_wprep(
    const float* __restrict__ Wq, const float* __restrict__ Wk,
    const float* __restrict__ Wv, const float* __restrict__ Wout)
{
    const int job = blockIdx.y;
    int o = blockIdx.x * 256 + threadIdx.x;            // 65536
    __nv_bfloat16 h, l;
    if (job < 3) {
        const float* W = (job == 0) ? Wq : (job == 1) ? Wk : Wv;
        int n = o >> 10, k = o & 1023;
        split_bf16(W[k * HD + n], h, l);
        g_wth[job][o] = h; g_wtl[job][o] = l;
    } else {
        int d = o >> 10, j = o & 1023;                 // coalesced Wout reads over j
        float s = 0.f;
#pragma unroll
        for (int hh = 0; hh < NH; hh++) s += Wout[(hh * HD + d) * HID + j];
        split_bf16(s, h, l);
        g_wfth[j * HD + d] = h; g_wftl[j * HD + d] = l;
    }
}

// ---------------- projections via HMMA 3-term --------------------------------
// M-tile 128, N=64, K=1024 in 16 chunks of 64. grid (64, 3), 256 threads.
// smem: XH 0, XL 16K, WH 32K, WL 40K  (48KB)
__global__ __launch_bounds__(256) void k_proj_mma(
    const float* __restrict__ Xq, const float* __restrict__ Xk, const float* __restrict__ Xv,
    const float* __restrict__ Bq, const float* __restrict__ Bk, const float* __restrict__ Bv)
{
    extern __shared__ __align__(1024) char smem[];
    const int XH = 0, XL = 16384, WH = 32768, WL = 40960;
    const uint32_t sb = smem_u32(smem);
    const int tid = threadIdx.x, w = tid >> 5, lane = tid & 31;
    const int which = blockIdx.y, m0 = blockIdx.x * 128;

    const float* X  = (which == 0) ? Xq : (which == 1) ? Xk : Xv;
    const float* Bb = (which == 0) ? Bq : (which == 1) ? Bk : Bv;
    const __nv_bfloat16* Wth = g_wth[which];
    const __nv_bfloat16* Wtl = g_wtl[which];

    const int xr = tid >> 1, xh2 = tid & 1;            // 2 threads per X row
    float c[8][4] = {};

    for (int kc = 0; kc < 16; kc++) {
        const int k0 = kc * 64;
        if (kc) __syncthreads();
        // stage X 128x64 fp32 -> hi/lo bf16 swizzled
        const float4* src = (const float4*)(X + (size_t)(m0 + xr) * HID + k0 + xh2 * 32);
#pragma unroll
        for (int i = 0; i < 8; i++) {
            float4 x = src[i];
            __nv_bfloat16 h0, l0, h1, l1, h2, l2, h3, l3;
            split_bf16(x.x, h0, l0); split_bf16(x.y, h1, l1);
            split_bf16(x.z, h2, l2); split_bf16(x.w, h3, l3);
            uint32_t so = SW128(xr * 128 + xh2 * 64 + i * 8);
            *(__nv_bfloat162*)(smem + XH + so)     = __nv_bfloat162(h0, h1);
            *(__nv_bfloat162*)(smem + XH + so + 4) = __nv_bfloat162(h2, h3);
            *(__nv_bfloat162*)(smem + XL + so)     = __nv_bfloat162(l0, l1);
            *(__nv_bfloat162*)(smem + XL + so + 4) = __nv_bfloat162(l2, l3);
        }
        // stage W^T 64x64 hi/lo
        for (int idx = tid; idx < 512; idx += 256) {
            int r = idx >> 3, cc = idx & 7;
            uint32_t so = SW128(r * 128 + cc * 16);
            *(uint4*)(smem + WH + so) = ((const uint4*)(Wth + (size_t)r * HID + k0))[cc];
            *(uint4*)(smem + WL + so) = ((const uint4*)(Wtl + (size_t)r * HID + k0))[cc];
        }
        __syncthreads();

        const int TA[3] = {XH, XL, XH}, TB[3] = {WH, WH, WL};
#pragma unroll
        for (int t = 0; t < 3; t++) {
            uint32_t ab = sb + TA[t], bb = sb + TB[t];
#pragma unroll
            for (int k16 = 0; k16 < 4; k16++) {
                int kb0 = k16 * 32;
                uint32_t a[4];
                ldsm_x4(a, a_addr(ab, lane, w * 16, kb0));
#pragma unroll
                for (int nj = 0; nj < 4; nj++) {
                    uint32_t r[4];
                    ldsm_x4(r, b_addr(bb, lane, nj * 16, kb0));
                    MMA16816(c[2 * nj],     a, r[0], r[1]);
                    MMA16816(c[2 * nj + 1], a, r[2], r[3]);
                }
            }
        }
    }

    // epilogue: +bias; q/k -> hi/lo bf16, v -> fp32
    const int q = lane >> 2, cpair = (lane & 3) * 2;
    const int row0 = m0 + w * 16 + q;
#pragma unroll
    for (int ni = 0; ni < 8; ni++) {
        int col = ni * 8 + cpair;
        float2 bias = *(const float2*)(Bb + col);
        float v0 = c[ni][0] + bias.x, v1 = c[ni][1] + bias.y;
        float v2 = c[ni][2] + bias.x, v3 = c[ni][3] + bias.y;
        if (which < 2) {
            __nv_bfloat16 h0, l0, h1, l1, h2, l2, h3, l3;
            split_bf16(v0, h0, l0); split_bf16(v1, h1, l1);
            split_bf16(v2, h2, l2); split_bf16(v3, h3, l3);
            __nv_bfloat16* H = which ? g_kh : g_qh;
            __nv_bfloat16* L = which ? g_kl : g_ql;
            size_t base = (size_t)blockIdx.z * 0;  // (unused; keep simple)
            (void)base;
            *(__nv_bfloat162*)(H + (size_t)row0 * HD + col)       = __nv_bfloat162(h0, h1);
            *(__nv_bfloat162*)(H + (size_t)(row0 + 8) * HD + col) = __nv_bfloat162(h2, h3);
            *(__nv_bfloat162*)(L + (size_t)row0 * HD + col)       = __nv_bfloat162(l0, l1);
            *(__nv_bfloat162*)(L + (size_t)(row0 + 8) * HD + col) = __nv_bfloat162(l2, l3);
        } else {
            *(float2*)(g_v + (size_t)row0 * HD + col)       = make_float2(v0, v1);
            *(float2*)(g_v + (size_t)(row0 + 8) * HD + col) = make_float2(v2, v3);
        }
    }
}

// ---------------- V transpose + split: [b][k][d] -> [b][d][k] hi/lo ----------
__global__ __launch_bounds__(256) void k_splitv() {
    int i4 = blockIdx.x * 256 + threadIdx.x;           // 131072
    int kq = i4 & 511, bd = i4 >> 9;                   // bd in [0,256)
    int b = bd >> 6, d = bd & 63, k0 = kq * 4;
    __nv_bfloat16 h[4], l[4];
#pragma unroll
    for (int i = 0; i < 4; i++)
        split_bf16(g_v[((size_t)(b * SEQ + k0 + i)) * HD + d], h[i], l[i]);
    size_t base = (size_t)bd * SEQ + k0;
    *(__nv_bfloat162*)(g_vth + base)     = __nv_bfloat162(h[0], h[1]);
    *(__nv_bfloat162*)(g_vth + base + 2) = __nv_bfloat162(h[2], h[3]);
    *(__nv_bfloat162*)(g_vtl + base)     = __nv_bfloat162(l[0], l[1]);
    *(__nv_bfloat162*)(g_vtl + base + 2) = __nv_bfloat162(l[2], l[3]);
}

// ---------------- scores via mma.sync 3-term + partial LN stats --------------
__global__ __launch_bounds__(256) void k_scores_mma() {
    extern __shared__ __align__(1024) char smem[];
    const int QH = 0, QL = 16384, KH = 32768, KL = 49152;
    const uint32_t sb = smem_u32(smem);
    const int tid = threadIdx.x, w = tid >> 5, lane = tid & 31;
    const int wm = w >> 1, wn = w & 1;
    const int nt = blockIdx.x, mt = blockIdx.y, b = blockIdx.z;
    const int i0 = mt * 128, j0 = nt * 128;
    const size_t qr0 = (size_t)b * SEQ + i0, kr0 = (size_t)b * SEQ + j0;

    for (int idx = tid; idx < 1024; idx += 256) {
        int r = idx >> 3, c = idx & 7;
        uint32_t so = SW128(r * 128 + c * 16);
        *(uint4*)(smem + QH + so) = ((const uint4*)(g_qh + (qr0 + r) * HD))[c];
        *(uint4*)(smem + QL + so) = ((const uint4*)(g_ql + (qr0 + r) * HD))[c];
        *(uint4*)(smem + KH + so) = ((const uint4*)(g_kh + (kr0 + r) * HD))[c];
        *(uint4*)(smem + KL + so) = ((const uint4*)(g_kl + (kr0 + r) * HD))[c];
    }
    __syncthreads();

    float c[2][8][4] = {};
    const int TA[3] = {QH, QL, QH}, TB[3] = {KH, KH, KL};
#pragma unroll
    for (int t = 0; t < 3; t++) {
        uint32_t ab = sb + TA[t], bb = sb + TB[t];
#pragma unroll
        for (int k16 = 0; k16 < 4; k16++) {
            int kb0 = k16 * 32;
            uint32_t a[2][4];
            ldsm_x4(a[0], a_addr(ab, lane, wm * 32, kb0));
            ldsm_x4(a[1], a_addr(ab, lane, wm * 32 + 16, kb0));
#pragma unroll
            for (int nj = 0; nj < 4; nj++) {
                uint32_t r[4];
                ldsm_x4(r, b_addr(bb, lane, wn * 64 + nj * 16, kb0));
                MMA16816(c[0][2 * nj],     a[0], r[0], r[1]);
                MMA16816(c[0][2 * nj + 1], a[0], r[2], r[3]);
                MMA16816(c[1][2 * nj],     a[1], r[0], r[1]);
                MMA16816(c[1][2 * nj + 1], a[1], r[2], r[3]);
            }
        }
    }

    const int q = lane >> 2, cpair = (lane & 3) * 2;
    float s1v[4] = {}, s2v[4] = {};
    float* Cb = g_sc + (size_t)b * SEQ * SEQ;
#pragma unroll
    for (int mi = 0; mi < 2; mi++) {
        int row0 = i0 + wm * 32 + mi * 16 + q;
#pragma unroll
        for (int ni = 0; ni < 8; ni++) {
            float* c4 = c[mi][ni];
            int col = j0 + wn * 64 + ni * 8 + cpair;
            *(float2*)(Cb + (size_t)row0 * SEQ + col)       = make_float2(c4[0], c4[1]);
            *(float2*)(Cb + (size_t)(row0 + 8) * SEQ + col) = make_float2(c4[2], c4[3]);
            s1v[mi * 2 + 0] += c4[0] + c4[1];
            s2v[mi * 2 + 0] += c4[0] * c4[0] + c4[1] * c4[1];
            s1v[mi * 2 + 1] += c4[2] + c4[3];
            s2v[mi * 2 + 1] += c4[2] * c4[2] + c4[3] * c4[3];
        }
    }
#pragma unroll
    for (int j = 0; j < 4; j++) {
        s1v[j] += __shfl_xor_sync(0xffffffffu, s1v[j], 1);
        s2v[j] += __shfl_xor_sync(0xffffffffu, s2v[j], 1);
        s1v[j] += __shfl_xor_sync(0xffffffffu, s1v[j], 2);
        s2v[j] += __shfl_xor_sync(0xffffffffu, s2v[j], 2);
    }
    if ((lane & 3) == 0) {
        const int sidx = nt * 2 + wn;
#pragma unroll
        for (int j = 0; j < 4; j++) {
            int mi = j >> 1, sub = j & 1;
            int row = i0 + wm * 32 + mi * 16 + sub * 8 + q;
            g_s1[sidx][b * SEQ + row] = s1v[j];
            g_s2[sidx][b * SEQ + row] = s2v[j];
        }
    }
}

// ---------------- reduce stats -> mean/isig ----------------------------------
__global__ __launch_bounds__(256) void k_stats() {
    int r = blockIdx.x * 256 + threadIdx.x;
    float s1 = 0.f, s2 = 0.f;
#pragma unroll
    for (int t = 0; t < NST; t++) { s1 += g_s1[t][r]; s2 += g_s2[t][r]; }
    float s1s = s1 * INV32, s2s = s2 * (INV32 * INV32);
    float mean = s1s * (1.f / 2048.f);
    float var  = (s2s - s1s * mean) * (1.f / 2047.f);
    g_mean[r] = mean;
    g_isig[r] = 1.f / (sqrtf(var) + 1e-8f);
}

// ---------------- attn@V via mma.sync, fused exp, split-K --------------------
__global__ __launch_bounds__(256) void k_attnv_mma() {
    extern __shared__ __align__(1024) char smem[];
    const int PH = 0, PL = 16384, VH = 32768, VL = 40960;
    const uint32_t sb = smem_u32(smem);
    const int tid = threadIdx.x, w = tid >> 5, lane = tid & 31;
    const int mt = blockIdx.x, ks = blockIdx.y, b = blockIdx.z;
    const int i0 = mt * 128, kbeg = ks * (SEQ / KS);

    float al = 0.f, be = 0.f, ps = 0.f;
    const float* Erow = nullptr;
    if (tid < 128) {
        int rowg = b * SEQ + i0 + tid;
        float is = g_isig[rowg];
        al = INV32 * is;
        be = -g_mean[rowg] * is;
        Erow = g_sc + (size_t)b * SEQ * SEQ + (size_t)(i0 + tid) * SEQ;
    }
    float c[8][4] = {};

    for (int st = 0; st < 4; st++) {
        const int k0 = kbeg + st * 64;
        if (st) __syncthreads();
        if (tid < 128) {
            const float4* E4 = (const float4*)(Erow + k0);
#pragma unroll
            for (int cc = 0; cc < 16; cc++) {
                float4 sv = E4[cc];
                float e0 = __expf(fmaf(sv.x, al, be));
                float e1 = __expf(fmaf(sv.y, al, be));
                float e2 = __expf(fmaf(sv.z, al, be));
                float e3 = __expf(fmaf(sv.w, al, be));
                ps += (e0 + e1) + (e2 + e3);
                __nv_bfloat16 h0, l0, h1, l1, h2, l2, h3, l3;
                split_bf16(e0, h0, l0); split_bf16(e1, h1, l1);
                split_bf16(e2, h2, l2); split_bf16(e3, h3, l3);
                uint32_t so = SW128(tid * 128 + cc * 8);
                *(__nv_bfloat162*)(smem + PH + so)     = __nv_bfloat162(h0, h1);
                *(__nv_bfloat162*)(smem + PH + so + 4) = __nv_bfloat162(h2, h3);
                *(__nv_bfloat162*)(smem + PL + so)     = __nv_bfloat162(l0, l1);
                *(__nv_bfloat162*)(smem + PL + so + 4) = __nv_bfloat162(l2, l3);
            }
        } else {
            int t2 = tid - 128;
            for (int idx = t2; idx < 512; idx += 128) {
                int r = idx >> 3, cc = idx & 7;
                uint32_t so = SW128(r * 128 + cc * 16);
                *(uint4*)(smem + VH + so) = ((const uint4*)(g_vth + ((size_t)(b * HD + r)) * SEQ + k0))[cc];
                *(uint4*)(smem + VL + so) = ((const uint4*)(g_vtl + ((size_t)(b * HD + r)) * SEQ + k0))[cc];
            }
        }
        __syncthreads();

        const int TA[3] = {PH, PL, PH}, TB[3] = {VH, VH, VL};
#pragma unroll
        for (int t = 0; t < 3; t++) {
            uint32_t ab = sb + TA[t], bb = sb + TB[t];
#pragma unroll
            for (int k16 = 0; k16 < 4; k16++) {
                int kb0 = k16 * 32;
                uint32_t a[4];
                ldsm_x4(a, a_addr(ab, lane, w * 16, kb0));
#pragma unroll
                for (int nj = 0; nj < 4; nj++) {
                    uint32_t r[4];
                    ldsm_x4(r, b_addr(bb, lane, nj * 16, kb0));
                    MMA16816(c[2 * nj],     a, r[0], r[1]);
                    MMA16816(c[2 * nj + 1], a, r[2], r[3]);
                }
            }
        }
    }

    if (tid < 128) g_esp[ks][b * SEQ + i0 + tid] = ps;

    const int q = lane >> 2, cpair = (lane & 3) * 2;
    float* O = g_hp[ks] + ((size_t)(b * SEQ + i0 + w * 16)) * HD;
#pragma unroll
    for (int ni = 0; ni < 8; ni++) {
        int col = ni * 8 + cpair;
        *(float2*)(O + (size_t)q * HD + col)       = make_float2(c[ni][0], c[ni][1]);
        *(float2*)(O + (size_t)(q + 8) * HD + col) = make_float2(c[ni][2], c[ni][3]);
    }
}

// ---------------- reduce split-K, normalize, split head to bf16 hi/lo --------
__global__ __launch_bounds__(256) void k_hred() {
    int idx = blockIdx.x * 256 + threadIdx.x;
    int row = idx >> 6;
    float tot = 0.f, s = 0.f;
#pragma unroll
    for (int t = 0; t < KS; t++) { tot += g_esp[t][row]; s += g_hp[t][idx]; }
    float val = s * (1.f / tot);
    __nv_bfloat16 h, l;
    split_bf16(val, h, l);
    g_hh[idx] = h; g_hl[idx] = l;
}

// ---------------- out = head @ Wfold + bout via HMMA 3-term ------------------
// tile 128x128, K=64 single stage. grid (8, 64), 256 threads, smem 64KB.
__global__ __launch_bounds__(256) void k_final_mma(float* __restrict__ out,
                                                   const float* __restrict__ bout) {
    extern __shared__ __align__(1024) char smem[];
    const int AH = 0, AL = 16384, BH = 32768, BL = 49152;
    const uint32_t sb = smem_u32(smem);
    const int tid = threadIdx.x, w = tid >> 5, lane = tid & 31;
    const int wm = w >> 1, wn = w & 1;
    const int m0 = blockIdx.y * 128, j0 = blockIdx.x * 128;

    for (int idx = tid; idx < 1024; idx += 256) {
        int r = idx >> 3, c = idx & 7;
        uint32_t so = SW128(r * 128 + c * 16);
        *(uint4*)(smem + AH + so) = ((const uint4*)(g_hh + (size_t)(m0 + r) * HD))[c];
        *(uint4*)(smem + AL + so) = ((const uint4*)(g_hl + (size_t)(m0 + r) * HD))[c];
        *(uint4*)(smem + BH + so) = ((const uint4*)(g_wfth + (size_t)(j0 + r) * HD))[c];
        *(uint4*)(smem + BL + so) = ((const uint4*)(g_wftl + (size_t)(j0 + r) * HD))[c];
    }
    __syncthreads();

    float c[2][8][4] = {};
    const int TA[3] = {AH, AL, AH}, TB[3] = {BH, BH, BL};
#pragma unroll
    for (int t = 0; t < 3; t++) {
        uint32_t ab = sb + TA[t], bb = sb + TB[t];
#pragma unroll
        for (int k16 = 0; k16 < 4; k16++) {
            int kb0 = k16 * 32;
            uint32_t a[2][4];
            ldsm_x4(a[0], a_addr(ab, lane, wm * 32, kb0));
            ldsm_x4(a[1], a_addr(ab, lane, wm * 32 + 16, kb0));
#pragma unroll
            for (int nj = 0; nj < 4; nj++) {
                uint32_t r[4];
                ldsm_x4(r, b_addr(bb, lane, wn * 64 + nj * 16, kb0));
                MMA16816(c[0][2 * nj],     a[0], r[0], r[1]);
                MMA16816(c[0][2 * nj + 1], a[0], r[2], r[3]);
                MMA16816(c[1][2 * nj],     a[1], r[0], r[1]);
                MMA16816(c[1][2 * nj + 1], a[1], r[2], r[3]);
            }
        }
    }

    const int q = lane >> 2, cpair = (lane & 3) * 2;
#pragma unroll
    for (int mi = 0; mi < 2; mi++) {
        int row0 = m0 + wm * 32 + mi * 16 + q;
#pragma unroll
        for (int ni = 0; ni < 8; ni++) {
            float* c4 = c[mi][ni];
            int col = j0 + wn * 64 + ni * 8 + cpair;
            float2 bias = *(const float2*)(bout + col);
            *(float2*)(out + (size_t)row0 * HID + col) =
                make_float2(c4[0] + bias.x, c4[1] + bias.y);
            *(float2*)(out + (size_t)(row0 + 8) * HID + col) =
                make_float2(c4[2] + bias.x, c4[3] + bias.y);
        }
    }
}

// ---------------------------------------------------------------------------
extern "C" void kernel_launch(void* const* d_in, const int* in_sizes, int n_in,
                              void* d_out, int out_size) {
    const float* query = (const float*)d_in[0];
    const float* key   = (const float*)d_in[1];
    const float* value = (const float*)d_in[2];
    // d_in[3] = mask: adding -1e-32 is a float32 no-op -> ignored
    const float* Wq    = (const float*)d_in[4];
    const float* bq    = (const float*)d_in[5];
    const float* Wk    = (const float*)d_in[6];
    const float* bk    = (const float*)d_in[7];
    const float* Wv    = (const float*)d_in[8];
    const float* bv    = (const float*)d_in[9];
    const float* Wout  = (const float*)d_in[10];
    const float* bout  = (const float*)d_in[11];
    // d_in[12] = seq_mask (0) -> ignored
    float* out = (float*)d_out;

    cudaFuncSetAttribute(k_proj_mma,   cudaFuncAttributeMaxDynamicSharedMemorySize, 49152);
    cudaFuncSetAttribute(k_scores_mma, cudaFuncAttributeMaxDynamicSharedMemorySize, 65536);
    cudaFuncSetAttribute(k_attnv_mma,  cudaFuncAttributeMaxDynamicSharedMemorySize, 49152);
    cudaFuncSetAttribute(k_final_mma,  cudaFuncAttributeMaxDynamicSharedMemorySize, 65536);

    k_wprep<<<dim3(256, 4), 256>>>(Wq, Wk, Wv, Wout);
    k_proj_mma<<<dim3(64, 3), 256, 49152>>>(query, key, value, bq, bk, bv);
    k_splitv<<<512, 256>>>();
    k_scores_mma<<<dim3(NT, 16, NB), 256, 65536>>>();
    k_stats<<<NB * SEQ / 256, 256>>>();
    k_attnv_mma<<<dim3(16, KS, NB), 256, 49152>>>();
    k_hred<<<(NB * SEQ * HD) / 256, 256>>>();
    k_final_mma<<<dim3(8, 64), 256, 65536>>>(out, bout);
}

// round 15
// speedup vs baseline: 1.3971x; 1.0588x over previous
#include <cuda_runtime.h>
#include <cuda_bf16.h>
#include <stdint.h>

#define NB   4
#define SEQ  2048
#define HID  1024
#define HD   64
#define NH   16
#define KS   8       // split-K for attn@V
#define NT   16      // j-tiles for scores (2048/128)
#define NST  64      // stat partials = NT * 4 warp-cols
#define INV32 0.03125f

// ---------------- base-target tensor-core helpers (NO tcgen05) --------------
__device__ __forceinline__ uint32_t smem_u32(const void* p) {
    uint32_t a;
    asm("{ .reg .u64 t; cvta.to.shared.u64 t, %1; cvt.u32.u64 %0, t; }" : "=r"(a) : "l"(p));
    return a;
}
#define SW128(o) ((o) ^ (((o) >> 3) & 0x70))

__device__ __forceinline__ void ldsm_x4(uint32_t r[4], uint32_t addr) {
    asm volatile("ldmatrix.sync.aligned.m8n8.x4.shared.b16 {%0,%1,%2,%3}, [%4];"
                 : "=r"(r[0]), "=r"(r[1]), "=r"(r[2]), "=r"(r[3]) : "r"(addr));
}
#define MMA16816(c, a, b0, b1) \
    asm volatile("mma.sync.aligned.m16n8k16.row.col.f32.bf16.bf16.f32 " \
        "{%0,%1,%2,%3}, {%4,%5,%6,%7}, {%8,%9}, {%0,%1,%2,%3};" \
        : "+f"((c)[0]), "+f"((c)[1]), "+f"((c)[2]), "+f"((c)[3]) \
        : "r"((a)[0]), "r"((a)[1]), "r"((a)[2]), "r"((a)[3]), "r"(b0), "r"(b1))

__device__ __forceinline__ uint32_t a_addr(uint32_t base, int lane, int m0, int kb0) {
    int row = m0 + (lane & 15);
    int kb  = kb0 + ((lane >> 4) << 4);
    return base + SW128(row * 128 + kb);
}
__device__ __forceinline__ uint32_t b_addr(uint32_t base, int lane, int n0, int kb0) {
    int n  = n0 + (lane & 7) + ((lane >> 4) << 3);
    int kb = kb0 + ((lane & 8) ? 16 : 0);
    return base + SW128(n * 128 + kb);
}
__device__ __forceinline__ void split_bf16(float x, __nv_bfloat16& h, __nv_bfloat16& l) {
    h = __float2bfloat16(x);
    l = __float2bfloat16(x - __bfloat162float(h));
}

// ---------------- scratch ---------------------------------------------------
static __device__ float g_v[NB * SEQ * HD];
static __device__ __nv_bfloat16 g_qh[NB * SEQ * HD], g_ql[NB * SEQ * HD];
static __device__ __nv_bfloat16 g_kh[NB * SEQ * HD], g_kl[NB * SEQ * HD];
static __device__ __nv_bfloat16 g_vth[NB * HD * SEQ], g_vtl[NB * HD * SEQ];  // [b][d][k]
static __device__ __nv_bfloat16 g_wth[3][HD * HID], g_wtl[3][HD * HID];      // W^T [n][k]
static __device__ __nv_bfloat16 g_wfth[HID * HD], g_wftl[HID * HD];          // Wfold^T [j][d]
static __device__ float g_sc[(size_t)NB * SEQ * SEQ];
static __device__ float g_s1[NST][NB * SEQ], g_s2[NST][NB * SEQ];
static __device__ float g_mean[NB * SEQ], g_isig[NB * SEQ];
static __device__ float g_esp[KS][NB * SEQ];
static __device__ float g_hp[KS][NB * SEQ * HD];
static __device__ __nv_bfloat16 g_hh[NB * SEQ * HD], g_hl[NB * SEQ * HD];    // head hi/lo

// ---------------- weight prep: transpose + hi/lo split + Wfold ---------------
__global__ __launch_bounds__(256) void k_wprep(
    const float* __restrict__ Wq, const float* __restrict__ Wk,
    const float* __restrict__ Wv, const float* __restrict__ Wout)
{
    const int job = blockIdx.y;
    int o = blockIdx.x * 256 + threadIdx.x;            // 65536
    __nv_bfloat16 h, l;
    if (job < 3) {
        const float* W = (job == 0) ? Wq : (job == 1) ? Wk : Wv;
        int n = o >> 10, k = o & 1023;
        split_bf16(W[k * HD + n], h, l);
        g_wth[job][o] = h; g_wtl[job][o] = l;
    } else {
        int d = o >> 10, j = o & 1023;
        float s = 0.f;
#pragma unroll
        for (int hh = 0; hh < NH; hh++) s += Wout[(hh * HD + d) * HID + j];
        split_bf16(s, h, l);
        g_wfth[j * HD + d] = h; g_wftl[j * HD + d] = l;
    }
}

// ---------------- projections via HMMA 3-term, 512 threads / 16 warps --------
// M-tile 128, N=64, K=1024 in 16 chunks of 64. grid (64, 3).
// warps: wm = w>>1 (16 rows), wn = w&1 (32 cols). acc 16/thread.
// smem: XH 0, XL 16K, WH 32K, WL 40K  (48KB)
__global__ __launch_bounds__(512) void k_proj_mma(
    const float* __restrict__ Xq, const float* __restrict__ Xk, const float* __restrict__ Xv,
    const float* __restrict__ Bq, const float* __restrict__ Bk, const float* __restrict__ Bv)
{
    extern __shared__ __align__(1024) char smem[];
    const int XH = 0, XL = 16384, WH = 32768, WL = 40960;
    const uint32_t sb = smem_u32(smem);
    const int tid = threadIdx.x, w = tid >> 5, lane = tid & 31;
    const int wm = w >> 1, wn = w & 1;
    const int which = blockIdx.y, m0 = blockIdx.x * 128;

    const float* X  = (which == 0) ? Xq : (which == 1) ? Xk : Xv;
    const float* Bb = (which == 0) ? Bq : (which == 1) ? Bk : Bv;
    const __nv_bfloat16* Wth = g_wth[which];
    const __nv_bfloat16* Wtl = g_wtl[which];

    float c[4][4] = {};

    for (int kc = 0; kc < 16; kc++) {
        const int k0 = kc * 64;
        if (kc) __syncthreads();
        if (tid < 256) {
            // stage X 128x64 fp32 -> hi/lo bf16 swizzled: row tid>>1, half (tid&1)*32
            const int xr = tid >> 1, xh2 = tid & 1;
            const float4* src = (const float4*)(X + (size_t)(m0 + xr) * HID + k0 + xh2 * 32);
#pragma unroll
            for (int i = 0; i < 8; i++) {
                float4 x = src[i];
                __nv_bfloat16 h0, l0, h1, l1, h2, l2, h3, l3;
                split_bf16(x.x, h0, l0); split_bf16(x.y, h1, l1);
                split_bf16(x.z, h2, l2); split_bf16(x.w, h3, l3);
                uint32_t so = SW128(xr * 128 + xh2 * 64 + i * 8);
                *(__nv_bfloat162*)(smem + XH + so)     = __nv_bfloat162(h0, h1);
                *(__nv_bfloat162*)(smem + XH + so + 4) = __nv_bfloat162(h2, h3);
                *(__nv_bfloat162*)(smem + XL + so)     = __nv_bfloat162(l0, l1);
                *(__nv_bfloat162*)(smem + XL + so + 4) = __nv_bfloat162(l2, l3);
            }
        } else {
            // stage W^T 64x64 hi/lo
            int t2 = tid - 256;
            for (int idx = t2; idx < 512; idx += 256) {
                int r = idx >> 3, cc = idx & 7;
                uint32_t so = SW128(r * 128 + cc * 16);
                *(uint4*)(smem + WH + so) = ((const uint4*)(Wth + (size_t)r * HID + k0))[cc];
                *(uint4*)(smem + WL + so) = ((const uint4*)(Wtl + (size_t)r * HID + k0))[cc];
            }
        }
        __syncthreads();

        const int TA[3] = {XH, XL, XH}, TB[3] = {WH, WH, WL};
#pragma unroll
        for (int t = 0; t < 3; t++) {
            uint32_t ab = sb + TA[t], bb = sb + TB[t];
#pragma unroll
            for (int k16 = 0; k16 < 4; k16++) {
                int kb0 = k16 * 32;
                uint32_t a[4];
                ldsm_x4(a, a_addr(ab, lane, wm * 16, kb0));
#pragma unroll
                for (int nj = 0; nj < 2; nj++) {
                    uint32_t r[4];
                    ldsm_x4(r, b_addr(bb, lane, wn * 32 + nj * 16, kb0));
                    MMA16816(c[2 * nj],     a, r[0], r[1]);
                    MMA16816(c[2 * nj + 1], a, r[2], r[3]);
                }
            }
        }
    }

    // epilogue: +bias; q/k -> hi/lo bf16, v -> fp32
    const int q = lane >> 2, cpair = (lane & 3) * 2;
    const int row0 = m0 + wm * 16 + q;
#pragma unroll
    for (int ni = 0; ni < 4; ni++) {
        int col = wn * 32 + ni * 8 + cpair;
        float2 bias = *(const float2*)(Bb + col);
        float v0 = c[ni][0] + bias.x, v1 = c[ni][1] + bias.y;
        float v2 = c[ni][2] + bias.x, v3 = c[ni][3] + bias.y;
        if (which < 2) {
            __nv_bfloat16 h0, l0, h1, l1, h2, l2, h3, l3;
            split_bf16(v0, h0, l0); split_bf16(v1, h1, l1);
            split_bf16(v2, h2, l2); split_bf16(v3, h3, l3);
            __nv_bfloat16* H = which ? g_kh : g_qh;
            __nv_bfloat16* L = which ? g_kl : g_ql;
            *(__nv_bfloat162*)(H + (size_t)row0 * HD + col)       = __nv_bfloat162(h0, h1);
            *(__nv_bfloat162*)(H + (size_t)(row0 + 8) * HD + col) = __nv_bfloat162(h2, h3);
            *(__nv_bfloat162*)(L + (size_t)row0 * HD + col)       = __nv_bfloat162(l0, l1);
            *(__nv_bfloat162*)(L + (size_t)(row0 + 8) * HD + col) = __nv_bfloat162(l2, l3);
        } else {
            *(float2*)(g_v + (size_t)row0 * HD + col)       = make_float2(v0, v1);
            *(float2*)(g_v + (size_t)(row0 + 8) * HD + col) = make_float2(v2, v3);
        }
    }
}

// ---------------- V transpose + split: [b][k][d] -> [b][d][k] hi/lo ----------
__global__ __launch_bounds__(256) void k_splitv() {
    int i4 = blockIdx.x * 256 + threadIdx.x;           // 131072
    int kq = i4 & 511, bd = i4 >> 9;
    int b = bd >> 6, d = bd & 63, k0 = kq * 4;
    __nv_bfloat16 h[4], l[4];
#pragma unroll
    for (int i = 0; i < 4; i++)
        split_bf16(g_v[((size_t)(b * SEQ + k0 + i)) * HD + d], h[i], l[i]);
    size_t base = (size_t)bd * SEQ + k0;
    *(__nv_bfloat162*)(g_vth + base)     = __nv_bfloat162(h[0], h[1]);
    *(__nv_bfloat162*)(g_vth + base + 2) = __nv_bfloat162(h[2], h[3]);
    *(__nv_bfloat162*)(g_vtl + base)     = __nv_bfloat162(l[0], l[1]);
    *(__nv_bfloat162*)(g_vtl + base + 2) = __nv_bfloat162(l[2], l[3]);
}

// ---------------- scores via HMMA 3-term, 512 threads / 16 warps -------------
// tile 128x128, warps 4x4 (wm rows of 32, wn cols of 32). acc 32/thread.
__global__ __launch_bounds__(512) void k_scores_mma() {
    extern __shared__ __align__(1024) char smem[];
    const int QH = 0, QL = 16384, KH = 32768, KL = 49152;
    const uint32_t sb = smem_u32(smem);
    const int tid = threadIdx.x, w = tid >> 5, lane = tid & 31;
    const int wm = w >> 2, wn = w & 3;
    const int nt = blockIdx.x, mt = blockIdx.y, b = blockIdx.z;
    const int i0 = mt * 128, j0 = nt * 128;
    const size_t qr0 = (size_t)b * SEQ + i0, kr0 = (size_t)b * SEQ + j0;

    for (int idx = tid; idx < 1024; idx += 512) {
        int r = idx >> 3, c = idx & 7;
        uint32_t so = SW128(r * 128 + c * 16);
        *(uint4*)(smem + QH + so) = ((const uint4*)(g_qh + (qr0 + r) * HD))[c];
        *(uint4*)(smem + QL + so) = ((const uint4*)(g_ql + (qr0 + r) * HD))[c];
        *(uint4*)(smem + KH + so) = ((const uint4*)(g_kh + (kr0 + r) * HD))[c];
        *(uint4*)(smem + KL + so) = ((const uint4*)(g_kl + (kr0 + r) * HD))[c];
    }
    __syncthreads();

    float c[2][4][4] = {};
    const int TA[3] = {QH, QL, QH}, TB[3] = {KH, KH, KL};
#pragma unroll
    for (int t = 0; t < 3; t++) {
        uint32_t ab = sb + TA[t], bb = sb + TB[t];
#pragma unroll
        for (int k16 = 0; k16 < 4; k16++) {
            int kb0 = k16 * 32;
            uint32_t a[2][4];
            ldsm_x4(a[0], a_addr(ab, lane, wm * 32, kb0));
            ldsm_x4(a[1], a_addr(ab, lane, wm * 32 + 16, kb0));
#pragma unroll
            for (int nj = 0; nj < 2; nj++) {
                uint32_t r[4];
                ldsm_x4(r, b_addr(bb, lane, wn * 32 + nj * 16, kb0));
                MMA16816(c[0][2 * nj],     a[0], r[0], r[1]);
                MMA16816(c[0][2 * nj + 1], a[0], r[2], r[3]);
                MMA16816(c[1][2 * nj],     a[1], r[0], r[1]);
                MMA16816(c[1][2 * nj + 1], a[1], r[2], r[3]);
            }
        }
    }

    const int q = lane >> 2, cpair = (lane & 3) * 2;
    float s1v[4] = {}, s2v[4] = {};
    float* Cb = g_sc + (size_t)b * SEQ * SEQ;
#pragma unroll
    for (int mi = 0; mi < 2; mi++) {
        int row0 = i0 + wm * 32 + mi * 16 + q;
#pragma unroll
        for (int ni = 0; ni < 4; ni++) {
            float* c4 = c[mi][ni];
            int col = j0 + wn * 32 + ni * 8 + cpair;
            *(float2*)(Cb + (size_t)row0 * SEQ + col)       = make_float2(c4[0], c4[1]);
            *(float2*)(Cb + (size_t)(row0 + 8) * SEQ + col) = make_float2(c4[2], c4[3]);
            s1v[mi * 2 + 0] += c4[0] + c4[1];
            s2v[mi * 2 + 0] += c4[0] * c4[0] + c4[1] * c4[1];
            s1v[mi * 2 + 1] += c4[2] + c4[3];
            s2v[mi * 2 + 1] += c4[2] * c4[2] + c4[3] * c4[3];
        }
    }
#pragma unroll
    for (int j = 0; j < 4; j++) {
        s1v[j] += __shfl_xor_sync(0xffffffffu, s1v[j], 1);
        s2v[j] += __shfl_xor_sync(0xffffffffu, s2v[j], 1);
        s1v[j] += __shfl_xor_sync(0xffffffffu, s1v[j], 2);
        s2v[j] += __shfl_xor_sync(0xffffffffu, s2v[j], 2);
    }
    if ((lane & 3) == 0) {
        const int sidx = nt * 4 + wn;
#pragma unroll
        for (int j = 0; j < 4; j++) {
            int mi = j >> 1, sub = j & 1;
            int row = i0 + wm * 32 + mi * 16 + sub * 8 + q;
            g_s1[sidx][b * SEQ + row] = s1v[j];
            g_s2[sidx][b * SEQ + row] = s2v[j];
        }
    }
}

// ---------------- reduce stats -> mean/isig ----------------------------------
__global__ __launch_bounds__(256) void k_stats() {
    int r = blockIdx.x * 256 + threadIdx.x;
    float s1 = 0.f, s2 = 0.f;
#pragma unroll
    for (int t = 0; t < NST; t++) { s1 += g_s1[t][r]; s2 += g_s2[t][r]; }
    float s1s = s1 * INV32, s2s = s2 * (INV32 * INV32);
    float mean = s1s * (1.f / 2048.f);
    float var  = (s2s - s1s * mean) * (1.f / 2047.f);
    g_mean[r] = mean;
    g_isig[r] = 1.f / (sqrtf(var) + 1e-8f);
}

// ---------------- attn@V via HMMA, fused exp, split-K, 512 threads -----------
// block M=128 x N=64. warps: wm = w>>1 (16 rows), wn = w&1 (32 cols).
__global__ __launch_bounds__(512) void k_attnv_mma() {
    extern __shared__ __align__(1024) char smem[];
    const int PH = 0, PL = 16384, VH = 32768, VL = 40960;
    const uint32_t sb = smem_u32(smem);
    const int tid = threadIdx.x, w = tid >> 5, lane = tid & 31;
    const int wm = w >> 1, wn = w & 1;
    const int mt = blockIdx.x, ks = blockIdx.y, b = blockIdx.z;
    const int i0 = mt * 128, kbeg = ks * (SEQ / KS);

    float al = 0.f, be = 0.f, ps = 0.f;
    const float* Erow = nullptr;
    int prow = 0, phalf = 0;
    if (tid < 256) {
        prow = tid >> 1; phalf = tid & 1;
        int rowg = b * SEQ + i0 + prow;
        float is = g_isig[rowg];
        al = INV32 * is;
        be = -g_mean[rowg] * is;
        Erow = g_sc + (size_t)b * SEQ * SEQ + (size_t)(i0 + prow) * SEQ + phalf * 32;
    }
    float c[4][4] = {};

    for (int st = 0; st < 4; st++) {
        const int k0 = kbeg + st * 64;
        if (st) __syncthreads();
        if (tid < 256) {
            // P tile: half row per thread (32 cols), exp + hi/lo split
            const float4* E4 = (const float4*)(Erow + k0);
#pragma unroll
            for (int cc = 0; cc < 8; cc++) {
                float4 sv = E4[cc];
                float e0 = __expf(fmaf(sv.x, al, be));
                float e1 = __expf(fmaf(sv.y, al, be));
                float e2 = __expf(fmaf(sv.z, al, be));
                float e3 = __expf(fmaf(sv.w, al, be));
                ps += (e0 + e1) + (e2 + e3);
                __nv_bfloat16 h0, l0, h1, l1, h2, l2, h3, l3;
                split_bf16(e0, h0, l0); split_bf16(e1, h1, l1);
                split_bf16(e2, h2, l2); split_bf16(e3, h3, l3);
                uint32_t so = SW128(prow * 128 + phalf * 64 + cc * 8);
                *(__nv_bfloat162*)(smem + PH + so)     = __nv_bfloat162(h0, h1);
                *(__nv_bfloat162*)(smem + PH + so + 4) = __nv_bfloat162(h2, h3);
                *(__nv_bfloat162*)(smem + PL + so)     = __nv_bfloat162(l0, l1);
                *(__nv_bfloat162*)(smem + PL + so + 4) = __nv_bfloat162(l2, l3);
            }
        } else {
            int t2 = tid - 256;
            for (int idx = t2; idx < 512; idx += 256) {
                int r = idx >> 3, cc = idx & 7;
                uint32_t so = SW128(r * 128 + cc * 16);
                *(uint4*)(smem + VH + so) = ((const uint4*)(g_vth + ((size_t)(b * HD + r)) * SEQ + k0))[cc];
                *(uint4*)(smem + VL + so) = ((const uint4*)(g_vtl + ((size_t)(b * HD + r)) * SEQ + k0))[cc];
            }
        }
        __syncthreads();

        const int TA[3] = {PH, PL, PH}, TB[3] = {VH, VH, VL};
#pragma unroll
        for (int t = 0; t < 3; t++) {
            uint32_t ab = sb + TA[t], bb = sb + TB[t];
#pragma unroll
            for (int k16 = 0; k16 < 4; k16++) {
                int kb0 = k16 * 32;
                uint32_t a[4];
                ldsm_x4(a, a_addr(ab, lane, wm * 16, kb0));
#pragma unroll
                for (int nj = 0; nj < 2; nj++) {
                    uint32_t r[4];
                    ldsm_x4(r, b_addr(bb, lane, wn * 32 + nj * 16, kb0));
                    MMA16816(c[2 * nj],     a, r[0], r[1]);
                    MMA16816(c[2 * nj + 1], a, r[2], r[3]);
                }
            }
        }
    }

    // partial expsum: pair threads (tid, tid^1) share a row
    ps += __shfl_xor_sync(0xffffffffu, ps, 1);
    if (tid < 256 && phalf == 0) g_esp[ks][b * SEQ + i0 + prow] = ps;

    const int q = lane >> 2, cpair = (lane & 3) * 2;
    float* O = g_hp[ks] + ((size_t)(b * SEQ + i0 + wm * 16)) * HD;
#pragma unroll
    for (int ni = 0; ni < 4; ni++) {
        int col = wn * 32 + ni * 8 + cpair;
        *(float2*)(O + (size_t)q * HD + col)       = make_float2(c[ni][0], c[ni][1]);
        *(float2*)(O + (size_t)(q + 8) * HD + col) = make_float2(c[ni][2], c[ni][3]);
    }
}

// ---------------- reduce split-K, normalize, split head to bf16 hi/lo --------
__global__ __launch_bounds__(256) void k_hred() {
    int idx = blockIdx.x * 256 + threadIdx.x;
    int row = idx >> 6;
    float tot = 0.f, s = 0.f;
#pragma unroll
    for (int t = 0; t < KS; t++) { tot += g_esp[t][row]; s += g_hp[t][idx]; }
    float val = s * (1.f / tot);
    __nv_bfloat16 h, l;
    split_bf16(val, h, l);
    g_hh[idx] = h; g_hl[idx] = l;
}

// ---------------- out = head @ Wfold + bout via HMMA 3-term, 512 thr ---------
// tile 128x128, K=64 single stage. warps 4x4 (32x32 tiles). grid (8, 64).
__global__ __launch_bounds__(512) void k_final_mma(float* __restrict__ out,
                                                   const float* __restrict__ bout) {
    extern __shared__ __align__(1024) char smem[];
    const int AH = 0, AL = 16384, BH = 32768, BL = 49152;
    const uint32_t sb = smem_u32(smem);
    const int tid = threadIdx.x, w = tid >> 5, lane = tid & 31;
    const int wm = w >> 2, wn = w & 3;
    const int m0 = blockIdx.y * 128, j0 = blockIdx.x * 128;

    for (int idx = tid; idx < 1024; idx += 512) {
        int r = idx >> 3, c = idx & 7;
        uint32_t so = SW128(r * 128 + c * 16);
        *(uint4*)(smem + AH + so) = ((const uint4*)(g_hh + (size_t)(m0 + r) * HD))[c];
        *(uint4*)(smem + AL + so) = ((const uint4*)(g_hl + (size_t)(m0 + r) * HD))[c];
        *(uint4*)(smem + BH + so) = ((const uint4*)(g_wfth + (size_t)(j0 + r) * HD))[c];
        *(uint4*)(smem + BL + so) = ((const uint4*)(g_wftl + (size_t)(j0 + r) * HD))[c];
    }
    __syncthreads();

    float c[2][4][4] = {};
    const int TA[3] = {AH, AL, AH}, TB[3] = {BH, BH, BL};
#pragma unroll
    for (int t = 0; t < 3; t++) {
        uint32_t ab = sb + TA[t], bb = sb + TB[t];
#pragma unroll
        for (int k16 = 0; k16 < 4; k16++) {
            int kb0 = k16 * 32;
            uint32_t a[2][4];
            ldsm_x4(a[0], a_addr(ab, lane, wm * 32, kb0));
            ldsm_x4(a[1], a_addr(ab, lane, wm * 32 + 16, kb0));
#pragma unroll
            for (int nj = 0; nj < 2; nj++) {
                uint32_t r[4];
                ldsm_x4(r, b_addr(bb, lane, wn * 32 + nj * 16, kb0));
                MMA16816(c[0][2 * nj],     a[0], r[0], r[1]);
                MMA16816(c[0][2 * nj + 1], a[0], r[2], r[3]);
                MMA16816(c[1][2 * nj],     a[1], r[0], r[1]);
                MMA16816(c[1][2 * nj + 1], a[1], r[2], r[3]);
            }
        }
    }

    const int q = lane >> 2, cpair = (lane & 3) * 2;
#pragma unroll
    for (int mi = 0; mi < 2; mi++) {
        int row0 = m0 + wm * 32 + mi * 16 + q;
#pragma unroll
        for (int ni = 0; ni < 4; ni++) {
            float* c4 = c[mi][ni];
            int col = j0 + wn * 32 + ni * 8 + cpair;
            float2 bias = *(const float2*)(bout + col);
            *(float2*)(out + (size_t)row0 * HID + col) =
                make_float2(c4[0] + bias.x, c4[1] + bias.y);
            *(float2*)(out + (size_t)(row0 + 8) * HID + col) =
                make_float2(c4[2] + bias.x, c4[3] + bias.y);
        }
    }
}

// ---------------------------------------------------------------------------
extern "C" void kernel_launch(void* const* d_in, const int* in_sizes, int n_in,
                              void* d_out, int out_size) {
    const float* query = (const float*)d_in[0];
    const float* key   = (const float*)d_in[1];
    const float* value = (const float*)d_in[2];
    // d_in[3] = mask: adding -1e-32 is a float32 no-op -> ignored
    const float* Wq    = (const float*)d_in[4];
    const float* bq    = (const float*)d_in[5];
    const float* Wk    = (const float*)d_in[6];
    const float* bk    = (const float*)d_in[7];
    const float* Wv    = (const float*)d_in[8];
    const float* bv    = (const float*)d_in[9];
    const float* Wout  = (const float*)d_in[10];
    const float* bout  = (const float*)d_in[11];
    // d_in[12] = seq_mask (0) -> ignored
    float* out = (float*)d_out;

    cudaFuncSetAttribute(k_proj_mma,   cudaFuncAttributeMaxDynamicSharedMemorySize, 49152);
    cudaFuncSetAttribute(k_scores_mma, cudaFuncAttributeMaxDynamicSharedMemorySize, 65536);
    cudaFuncSetAttribute(k_attnv_mma,  cudaFuncAttributeMaxDynamicSharedMemorySize, 49152);
    cudaFuncSetAttribute(k_final_mma,  cudaFuncAttributeMaxDynamicSharedMemorySize, 65536);

    k_wprep<<<dim3(256, 4), 256>>>(Wq, Wk, Wv, Wout);
    k_proj_mma<<<dim3(64, 3), 512, 49152>>>(query, key, value, bq, bk, bv);
    k_splitv<<<512, 256>>>();
    k_scores_mma<<<dim3(NT, 16, NB), 512, 65536>>>();
    k_stats<<<NB * SEQ / 256, 256>>>();
    k_attnv_mma<<<dim3(16, KS, NB), 512, 49152>>>();
    k_hred<<<(NB * SEQ * HD) / 256, 256>>>();
    k_final_mma<<<dim3(8, 64), 512, 65536>>>(out, bout);
}